// round 3
// baseline (speedup 1.0000x reference)
#include <cuda_runtime.h>
#include <math.h>

#define NN    1024
#define NE    4096
#define D     256
#define HN    4
#define DHD   64
#define NODEK 512
#define EDGEK 2048
#define CLS   16
#define MAXC  1024

// ---------------- scratch (static device allocations — allowed) ----------------
__device__ int   g_is64;
__device__ float g_nscore[NN];
__device__ float g_escore[NE];
__device__ int   g_nmask[NN];
__device__ int   g_emask[NE];
__device__ int   g_src[NE], g_dst[NE];
__device__ int   g_cnt[NN];
__device__ int   g_off[NN + 1];
__device__ int   g_inc[2 * NE];
__device__ float g_gs[NE * D];   // 0
__device__ float g_ef[NE * D];   // 1
__device__ float g_h[NE * D];    // 2
__device__ float g_q[NE * D];    // 3
__device__ float g_k[NE * D];    // 4
__device__ float g_v[NE * D];    // 5
__device__ float g_ao[NE * D];   // 6
__device__ float g_o[NE * D];    // 7
__device__ float g_hid[NE * D];  // 8

// device-side buffer selector (compile-time ID -> device global)
template <int ID> __device__ __forceinline__ float* buf();
template <> __device__ __forceinline__ float* buf<0>() { return g_gs; }
template <> __device__ __forceinline__ float* buf<1>() { return g_ef; }
template <> __device__ __forceinline__ float* buf<2>() { return g_h; }
template <> __device__ __forceinline__ float* buf<3>() { return g_q; }
template <> __device__ __forceinline__ float* buf<4>() { return g_k; }
template <> __device__ __forceinline__ float* buf<5>() { return g_v; }
template <> __device__ __forceinline__ float* buf<6>() { return g_ao; }
template <> __device__ __forceinline__ float* buf<7>() { return g_o; }
template <> __device__ __forceinline__ float* buf<8>() { return g_hid; }

// ---------------- -1: detect edge_index dtype (int32 vs int64) ----------------
// If the buffer is int64, every odd int32 word of the first 2048 pairs is the
// high word of a value < 1024, i.e. zero. If int32, those words are random
// values in [0,1024) — OR over 2048 of them is nonzero w.p. 1 - 1024^-2048.
// Reading 4096 int32 words is in-bounds for BOTH layouts (min size 8192 words).
__global__ void k_detect(const int* __restrict__ p) {
    __shared__ int sh[256];
    int t = threadIdx.x;
    int acc = 0;
    #pragma unroll
    for (int i = t; i < 2048; i += 256) acc |= p[2 * i + 1];
    sh[t] = acc;
    __syncthreads();
    for (int s = 128; s > 0; s >>= 1) {
        if (t < s) sh[t] |= sh[t + s];
        __syncthreads();
    }
    if (t == 0) g_is64 = (sh[0] == 0) ? 1 : 0;
}

// ---------------- 0: convert edge_index to int32, zero degree counts ----------------
__global__ void k_convert(const int* __restrict__ p) {
    int i = blockIdx.x * blockDim.x + threadIdx.x;
    if (i < NE) {
        if (g_is64) {
            g_src[i] = p[2 * i];
            g_dst[i] = p[2 * (NE + i)];
        } else {
            g_src[i] = p[i];
            g_dst[i] = p[NE + i];
        }
    }
    if (i < NN) g_cnt[i] = 0;
}

// ---------------- 1: router scores (one warp per row) ----------------
__global__ void k_scores(const float* __restrict__ nf, const float* __restrict__ ef,
                         const float* __restrict__ Wn, const float* __restrict__ bn,
                         const float* __restrict__ We, const float* __restrict__ be) {
    int warp = (blockIdx.x * blockDim.x + threadIdx.x) >> 5;
    int lane = threadIdx.x & 31;
    if (warp >= NN + NE) return;
    const float* x;
    const float* w;
    if (warp < NN) { x = nf + (size_t)warp * D; w = Wn; }
    else           { x = ef + (size_t)(warp - NN) * D; w = We; }
    float s = 0.f;
    #pragma unroll
    for (int i = 0; i < D / 32; ++i) s += x[lane + i * 32] * w[lane + i * 32];
    #pragma unroll
    for (int o = 16; o; o >>= 1) s += __shfl_xor_sync(0xffffffffu, s, o);
    if (lane == 0) {
        if (warp < NN) g_nscore[warp] = s + bn[0];
        else           g_escore[warp - NN] = s + be[0];
    }
}

// ---------------- 2: exact top-k mask (matches jax.lax.top_k incl. ties) ----------------
// blockIdx.x==0: nodes (n=1024,k=512); ==1: edges (n=4096,k=2048). 1024 threads.
__global__ void k_topk() {
    const bool is_edge = (blockIdx.x == 1);
    const float* sc = is_edge ? g_escore : g_nscore;
    int* mask = is_edge ? g_emask : g_nmask;
    const int n = is_edge ? NE : NN;
    const int kk = is_edge ? EDGEK : NODEK;

    __shared__ unsigned su[NE];
    __shared__ int red[1024];
    int tid = threadIdx.x;
    int items = n >> 10;  // 1 or 4

    for (int j = 0; j < items; ++j) {
        int i = tid * items + j;
        unsigned b = __float_as_uint(sc[i]);
        su[i] = (b & 0x80000000u) ? ~b : (b | 0x80000000u);  // order-preserving map
    }
    __syncthreads();

    // largest T with count(u >= T) >= kk  (T = k-th largest value)
    unsigned lo = 0u, hi = 0xFFFFFFFFu;
    while (lo < hi) {
        unsigned mid = lo + ((hi - lo) >> 1) + 1u;
        int c = 0;
        for (int j = 0; j < items; ++j) c += (su[tid * items + j] >= mid) ? 1 : 0;
        red[tid] = c;
        __syncthreads();
        for (int s = 512; s > 0; s >>= 1) {
            if (tid < s) red[tid] += red[tid + s];
            __syncthreads();
        }
        int total = red[0];
        __syncthreads();
        if (total >= kk) lo = mid; else hi = mid - 1u;
    }
    unsigned T = lo;

    // count strictly-greater, and per-thread tie count
    int cg = 0, ct = 0;
    for (int j = 0; j < items; ++j) {
        unsigned u = su[tid * items + j];
        cg += (u > T) ? 1 : 0;
        ct += (u == T) ? 1 : 0;
    }
    red[tid] = cg;
    __syncthreads();
    for (int s = 512; s > 0; s >>= 1) {
        if (tid < s) red[tid] += red[tid + s];
        __syncthreads();
    }
    int m = red[0];
    __syncthreads();
    int r = kk - m;  // number of tied elements to admit (lowest index first)

    // exclusive scan of tie counts (Hillis-Steele)
    red[tid] = ct;
    __syncthreads();
    int val = ct;
    for (int dd = 1; dd < 1024; dd <<= 1) {
        int t = (tid >= dd) ? red[tid - dd] : 0;
        __syncthreads();
        val += t;
        red[tid] = val;
        __syncthreads();
    }
    int excl = val - ct;

    for (int j = 0; j < items; ++j) {
        int i = tid * items + j;
        unsigned u = su[i];
        int mk;
        if (u > T) mk = 1;
        else if (u == T) { mk = (excl < r) ? 1 : 0; excl++; }
        else mk = 0;
        mask[i] = mk;
    }
}

// ---------------- 3: degree counts ----------------
__global__ void k_count() {
    int e = blockIdx.x * blockDim.x + threadIdx.x;
    if (e < NE) {
        atomicAdd(&g_cnt[g_src[e]], 1);
        if (g_dst[e] != g_src[e]) atomicAdd(&g_cnt[g_dst[e]], 1);
    }
}

// ---------------- 4: exclusive scan of counts -> offsets ----------------
__global__ void k_scan() {
    __shared__ int sh[1024];
    int tid = threadIdx.x;
    int own = g_cnt[tid];
    sh[tid] = own;
    __syncthreads();
    int val = own;
    for (int dd = 1; dd < 1024; dd <<= 1) {
        int t = (tid >= dd) ? sh[tid - dd] : 0;
        __syncthreads();
        val += t;
        sh[tid] = val;
        __syncthreads();
    }
    g_off[tid] = val - own;
    if (tid == 1023) g_off[1024] = val;
}

// ---------------- 5: deterministic incidence fill (one thread per node, index order) ----------------
__global__ void k_fill() {
    __shared__ int ss[NE], sd[NE];
    for (int i = threadIdx.x; i < NE; i += blockDim.x) { ss[i] = g_src[i]; sd[i] = g_dst[i]; }
    __syncthreads();
    int node = blockIdx.x * blockDim.x + threadIdx.x;
    if (node >= NN) return;
    int p = g_off[node];
    for (int e = 0; e < NE; ++e) {
        if (ss[e] == node || sd[e] == node) g_inc[p++] = e;
    }
}

// ---------------- 6: masked edge features + endpoint node-feature sums ----------------
__global__ void k_prepare(const float* __restrict__ nf, const float* __restrict__ efi) {
    int e = blockIdx.x;
    int d = threadIdx.x;
    int a = g_src[e], b = g_dst[e];
    int em = g_emask[e] & g_nmask[a] & g_nmask[b];
    g_ef[(size_t)e * D + d] = em ? efi[(size_t)e * D + d] : 0.f;
    g_gs[(size_t)e * D + d] = nf[(size_t)a * D + d] + nf[(size_t)b * D + d];
}

// ---------------- 7: fp32 tiled GEMM  C = A[MxK] @ B[KxN] + bias (+add) (+gelu) ----------------
// 64x64 block tile, 256 threads, 4x4 microtile, BK=16.
template <int ACT, int AID, int CID, int ADDID>
__global__ void k_gemm(const float* __restrict__ B, const float* __restrict__ bias) {
    const float* A = buf<AID>();
    float* C = buf<CID>();
    const float* add = (ADDID >= 0) ? buf<(ADDID >= 0 ? ADDID : 0)>() : nullptr;

    __shared__ float As[16 * 68];  // transposed: As[k][m]
    __shared__ float Bs[16 * 68];  // natural:    Bs[k][n]
    int tid = threadIdx.x;
    int tx = tid & 15, ty = tid >> 4;
    int m0 = blockIdx.y * 64, n0 = blockIdx.x * 64;
    float acc[4][4] = {};
    for (int k0 = 0; k0 < D; k0 += 16) {
        #pragma unroll
        for (int rep = 0; rep < 4; ++rep) {
            int lin = rep * 256 + tid;
            int m = lin >> 4, kk = lin & 15;
            As[kk * 68 + m] = A[(size_t)(m0 + m) * D + k0 + kk];
            int kk2 = lin >> 6, n = lin & 63;
            Bs[kk2 * 68 + n] = B[(size_t)(k0 + kk2) * D + n0 + n];
        }
        __syncthreads();
        #pragma unroll
        for (int kk = 0; kk < 16; ++kk) {
            float4 a4 = *(const float4*)&As[kk * 68 + ty * 4];
            float4 b4 = *(const float4*)&Bs[kk * 68 + tx * 4];
            float a[4] = {a4.x, a4.y, a4.z, a4.w};
            float b[4] = {b4.x, b4.y, b4.z, b4.w};
            #pragma unroll
            for (int i = 0; i < 4; ++i)
                #pragma unroll
                for (int j = 0; j < 4; ++j) acc[i][j] += a[i] * b[j];
        }
        __syncthreads();
    }
    #pragma unroll
    for (int i = 0; i < 4; ++i) {
        int m = m0 + ty * 4 + i;
        #pragma unroll
        for (int j = 0; j < 4; ++j) {
            int n = n0 + tx * 4 + j;
            float v = acc[i][j] + bias[n];
            if (ADDID >= 0) v += add[(size_t)m * D + n];
            if (ACT == 1) {  // gelu (tanh approximation, jax default)
                float x = v;
                float t = tanhf(0.7978845608028654f * (x + 0.044715f * x * x * x));
                v = 0.5f * x * (1.0f + t);
            }
            C[(size_t)m * D + n] = v;
        }
    }
}

// ---------------- 8: sparse masked attention (one block per edge, one warp per head) ----------------
// Non-adjacent entries contribute exp(-1e9 - max) == 0.0f exactly (also in the fp32
// reference), so softmax over the adjacency candidate set is exact.
__global__ void k_attn() {
    __shared__ int s_cand[MAXC];
    __shared__ float s_sc[HN][MAXC];
    __shared__ int s_n;
    int e = blockIdx.x;
    int tid = threadIdx.x;
    int h = tid >> 5, lane = tid & 31;
    int a = g_src[e], b = g_dst[e];
    int oa = g_off[a];
    int na = g_off[a + 1] - oa;

    // list A: all edges incident to a (adjacent by construction), index order
    for (int i = tid; i < na; i += 128) s_cand[i] = g_inc[oa + i];

    // list B: edges incident to b and NOT incident to a (dedupe), deterministic
    // ballot compaction by warp 0 (preserves index order)
    if (tid < 32) {
        int cnt = na;
        if (b != a) {
            int ob = g_off[b];
            int nb = g_off[b + 1] - ob;
            for (int i0 = 0; i0 < nb; i0 += 32) {
                int i = i0 + lane;
                int f = 0, keep = 0;
                if (i < nb) {
                    f = g_inc[ob + i];
                    keep = (g_src[f] != a && g_dst[f] != a) ? 1 : 0;
                }
                unsigned bal = __ballot_sync(0xffffffffu, keep != 0);
                if (keep) {
                    int pos = cnt + __popc(bal & ((1u << lane) - 1u));
                    if (pos < MAXC) s_cand[pos] = f;
                }
                cnt += __popc(bal);
            }
        }
        if (lane == 0) s_n = (cnt < MAXC) ? cnt : MAXC;
    }
    __syncthreads();
    int nc = s_n;
    int base = e * D + h * DHD;

    float2 q2 = *(const float2*)&g_q[base + lane * 2];

    // scores: whole warp per candidate (dot over 64 dims)
    for (int c = 0; c < nc; ++c) {
        int f = s_cand[c];
        float2 k2 = *(const float2*)&g_k[f * D + h * DHD + lane * 2];
        float s = q2.x * k2.x + q2.y * k2.y;
        #pragma unroll
        for (int o = 16; o; o >>= 1) s += __shfl_xor_sync(0xffffffffu, s, o);
        if (lane == 0) s_sc[h][c] = s * 0.125f;  // 1/sqrt(64)
    }
    __syncwarp();

    // softmax over candidates
    float mx = -3.0e38f;
    for (int c = lane; c < nc; c += 32) mx = fmaxf(mx, s_sc[h][c]);
    #pragma unroll
    for (int o = 16; o; o >>= 1) mx = fmaxf(mx, __shfl_xor_sync(0xffffffffu, mx, o));
    float l = 0.f;
    for (int c = lane; c < nc; c += 32) {
        float p = __expf(s_sc[h][c] - mx);
        s_sc[h][c] = p;
        l += p;
    }
    #pragma unroll
    for (int o = 16; o; o >>= 1) l += __shfl_xor_sync(0xffffffffu, l, o);
    __syncwarp();

    // weighted sum of V
    float ax = 0.f, ay = 0.f;
    for (int c = 0; c < nc; ++c) {
        float p = s_sc[h][c];
        float2 v2 = *(const float2*)&g_v[s_cand[c] * D + h * DHD + lane * 2];
        ax += p * v2.x;
        ay += p * v2.y;
    }
    float inv = 1.f / l;
    float2 r;
    r.x = ax * inv;
    r.y = ay * inv;
    *(float2*)&g_ao[base + lane * 2] = r;
}

// ---------------- 9: classifier  out = hid @ W2[256x16] + b2 (one warp per row) ----------------
__global__ void k_cls(const float* __restrict__ W2, const float* __restrict__ b2,
                      float* __restrict__ out) {
    int warp = (blockIdx.x * blockDim.x + threadIdx.x) >> 5;
    int lane = threadIdx.x & 31;
    if (warp >= NE) return;
    float x[8];
    #pragma unroll
    for (int i = 0; i < 8; ++i) x[i] = g_hid[(size_t)warp * D + lane + i * 32];
    float res = 0.f;
    #pragma unroll
    for (int c = 0; c < CLS; ++c) {
        float s = 0.f;
        #pragma unroll
        for (int i = 0; i < 8; ++i) s += x[i] * W2[(size_t)(lane + i * 32) * CLS + c];
        #pragma unroll
        for (int o = 16; o; o >>= 1) s += __shfl_xor_sync(0xffffffffu, s, o);
        if (lane == c) res = s + b2[c];
    }
    if (lane < CLS) out[(size_t)warp * CLS + lane] = res;
}

// ---------------- host ----------------
extern "C" void kernel_launch(void* const* d_in, const int* in_sizes, int n_in,
                              void* d_out, int out_size) {
    const float* nf   = (const float*)d_in[0];
    const float* efi  = (const float*)d_in[1];
    const int*   ei   = (const int*)d_in[2];   // int32 OR int64 — detected on device
    const float* Wn_r = (const float*)d_in[3];
    const float* bn_r = (const float*)d_in[4];
    const float* We_r = (const float*)d_in[5];
    const float* be_r = (const float*)d_in[6];
    const float* Wnp  = (const float*)d_in[7];
    const float* bnp  = (const float*)d_in[8];
    const float* Wq   = (const float*)d_in[9];
    const float* bq   = (const float*)d_in[10];
    const float* Wk   = (const float*)d_in[11];
    const float* bk   = (const float*)d_in[12];
    const float* Wv   = (const float*)d_in[13];
    const float* bv   = (const float*)d_in[14];
    const float* Wo   = (const float*)d_in[15];
    const float* bo   = (const float*)d_in[16];
    const float* W1   = (const float*)d_in[17];
    const float* b1   = (const float*)d_in[18];
    const float* W2   = (const float*)d_in[19];
    const float* b2   = (const float*)d_in[20];
    float* out = (float*)d_out;

    k_detect<<<1, 256>>>(ei);
    k_convert<<<(NE + 255) / 256, 256>>>(ei);
    k_scores<<<((NN + NE) * 32 + 255) / 256, 256>>>(nf, efi, Wn_r, bn_r, We_r, be_r);
    k_topk<<<2, 1024>>>();
    k_count<<<(NE + 255) / 256, 256>>>();
    k_scan<<<1, 1024>>>();
    k_fill<<<(NN + 255) / 256, 256>>>();
    k_prepare<<<NE, 256>>>(nf, efi);

    dim3 gg(D / 64, NE / 64);  // (4, 64)
    // h = gs @ Wnp + bnp + ef     (A=g_gs(0), C=g_h(2), add=g_ef(1))
    k_gemm<0, 0, 2, 1><<<gg, 256>>>(Wnp, bnp);
    // q, k, v                     (A=g_h(2))
    k_gemm<0, 2, 3, -1><<<gg, 256>>>(Wq, bq);
    k_gemm<0, 2, 4, -1><<<gg, 256>>>(Wk, bk);
    k_gemm<0, 2, 5, -1><<<gg, 256>>>(Wv, bv);
    // attention
    k_attn<<<NE, 128>>>();
    // o = ao @ Wo + bo            (A=g_ao(6), C=g_o(7))
    k_gemm<0, 6, 7, -1><<<gg, 256>>>(Wo, bo);
    // hid = gelu(o @ W1 + b1)     (A=g_o(7), C=g_hid(8))
    k_gemm<1, 7, 8, -1><<<gg, 256>>>(W1, b1);
    // out = hid @ W2 + b2
    k_cls<<<(NE * 32 + 255) / 256, 256>>>(W2, b2, out);
}

// round 4
// speedup vs baseline: 1.2056x; 1.2056x over previous
#include <cuda_runtime.h>
#include <math.h>

#define NN    1024
#define NE    4096
#define D     256
#define HN    4
#define DHD   64
#define NODEK 512
#define EDGEK 2048
#define CLS   16
#define MAXC  1024

// ---------------- scratch (static device allocations — allowed) ----------------
__device__ int   g_is64;
__device__ float g_nscore[NN];
__device__ float g_escore[NE];
__device__ int   g_nmask[NN];
__device__ int   g_emask[NE];
__device__ int   g_src[NE], g_dst[NE];
__device__ int   g_cnt[NN];
__device__ int   g_off[NN + 1];
__device__ int   g_inc[2 * NE];
__device__ float g_gs[NE * D];   // 0
__device__ float g_ef[NE * D];   // 1
__device__ float g_h[NE * D];    // 2
__device__ float g_q[NE * D];    // 3
__device__ float g_k[NE * D];    // 4
__device__ float g_v[NE * D];    // 5
__device__ float g_ao[NE * D];   // 6
__device__ float g_o[NE * D];    // 7
__device__ float g_hid[NE * D];  // 8

template <int ID> __device__ __forceinline__ float* buf();
template <> __device__ __forceinline__ float* buf<0>() { return g_gs; }
template <> __device__ __forceinline__ float* buf<1>() { return g_ef; }
template <> __device__ __forceinline__ float* buf<2>() { return g_h; }
template <> __device__ __forceinline__ float* buf<3>() { return g_q; }
template <> __device__ __forceinline__ float* buf<4>() { return g_k; }
template <> __device__ __forceinline__ float* buf<5>() { return g_v; }
template <> __device__ __forceinline__ float* buf<6>() { return g_ao; }
template <> __device__ __forceinline__ float* buf<7>() { return g_o; }
template <> __device__ __forceinline__ float* buf<8>() { return g_hid; }

// ---------------- -1: detect edge_index dtype (int32 vs int64) ----------------
__global__ void k_detect(const int* __restrict__ p) {
    __shared__ int sh[256];
    int t = threadIdx.x;
    int acc = 0;
    #pragma unroll
    for (int i = t; i < 2048; i += 256) acc |= p[2 * i + 1];
    sh[t] = acc;
    __syncthreads();
    for (int s = 128; s > 0; s >>= 1) {
        if (t < s) sh[t] |= sh[t + s];
        __syncthreads();
    }
    if (t == 0) g_is64 = (sh[0] == 0) ? 1 : 0;
}

// ---------------- 0: convert edge_index to int32, zero degree counts ----------------
__global__ void k_convert(const int* __restrict__ p) {
    int i = blockIdx.x * blockDim.x + threadIdx.x;
    if (i < NE) {
        if (g_is64) {
            g_src[i] = p[2 * i];
            g_dst[i] = p[2 * (NE + i)];
        } else {
            g_src[i] = p[i];
            g_dst[i] = p[NE + i];
        }
    }
    if (i < NN) g_cnt[i] = 0;
}

// ---------------- 1: router scores (one warp per row) ----------------
__global__ void k_scores(const float* __restrict__ nf, const float* __restrict__ ef,
                         const float* __restrict__ Wn, const float* __restrict__ bn,
                         const float* __restrict__ We, const float* __restrict__ be) {
    int warp = (blockIdx.x * blockDim.x + threadIdx.x) >> 5;
    int lane = threadIdx.x & 31;
    if (warp >= NN + NE) return;
    const float* x;
    const float* w;
    if (warp < NN) { x = nf + (size_t)warp * D; w = Wn; }
    else           { x = ef + (size_t)(warp - NN) * D; w = We; }
    float s = 0.f;
    #pragma unroll
    for (int i = 0; i < D / 32; ++i) s += x[lane + i * 32] * w[lane + i * 32];
    #pragma unroll
    for (int o = 16; o; o >>= 1) s += __shfl_xor_sync(0xffffffffu, s, o);
    if (lane == 0) {
        if (warp < NN) g_nscore[warp] = s + bn[0];
        else           g_escore[warp - NN] = s + be[0];
    }
}

// ---------------- 2: exact top-k via 4-pass MSB radix select ----------------
// blockIdx.x==0: nodes (n=1024,k=512); ==1: edges (n=4096,k=2048). 1024 threads.
// Matches jax.lax.top_k exactly, incl. lowest-index tie admission.
__global__ void k_topk() {
    const bool is_edge = (blockIdx.x == 1);
    const float* sc = is_edge ? g_escore : g_nscore;
    int* mask = is_edge ? g_emask : g_nmask;
    const int n = is_edge ? NE : NN;
    const int kk = is_edge ? EDGEK : NODEK;

    __shared__ unsigned su[NE];
    __shared__ int hist[256];
    __shared__ unsigned sh_pref;
    __shared__ int sh_krem;
    __shared__ int warp_agg[32];

    int tid = threadIdx.x;
    int lane = tid & 31, wid = tid >> 5;
    int items = n >> 10;  // 1 or 4

    for (int j = 0; j < items; ++j) {
        int i = tid * items + j;
        unsigned b = __float_as_uint(sc[i]);
        su[i] = (b & 0x80000000u) ? ~b : (b | 0x80000000u);  // order-preserving map
    }
    if (tid == 0) { sh_pref = 0u; sh_krem = kk; }
    __syncthreads();

    // 4 passes, MSB -> LSB: fix one byte of the k-th largest key per pass
    for (int shift = 24; shift >= 0; shift -= 8) {
        unsigned prefix = sh_pref;
        unsigned done_mask = (shift == 24) ? 0u : (0xFFFFFFFFu << (shift + 8));
        if (tid < 256) hist[tid] = 0;
        __syncthreads();
        for (int j = 0; j < items; ++j) {
            unsigned u = su[tid * items + j];
            if ((u & done_mask) == prefix)
                atomicAdd(&hist[(u >> shift) & 255], 1);
        }
        __syncthreads();
        if (wid == 0) {
            int krem = sh_krem;
            int gsum = 0;
            #pragma unroll
            for (int c = 0; c < 8; ++c) gsum += hist[lane * 8 + c];
            // inclusive suffix sum across lanes (lane g holds sum over groups >= g)
            int x = gsum;
            #pragma unroll
            for (int off = 1; off < 32; off <<= 1) {
                int t = __shfl_down_sync(0xffffffffu, x, off);
                if (lane + off < 32) x += t;
            }
            int above = x - gsum;  // elements in groups strictly above this one
            bool hit = (above < krem) && (x >= krem);  // exactly one lane
            unsigned bal = __ballot_sync(0xffffffffu, hit);
            int srcl = __ffs(bal) - 1;
            if (lane == srcl) {
                int cum = above;
                #pragma unroll
                for (int c = 7; c >= 0; --c) {
                    int b = lane * 8 + c;
                    int hc = hist[b];
                    if (cum + hc >= krem) {
                        sh_pref = prefix | ((unsigned)b << shift);
                        sh_krem = krem - cum;
                        break;
                    }
                    cum += hc;
                }
            }
        }
        __syncthreads();
    }
    unsigned T = sh_pref;       // exact k-th largest key
    int r = sh_krem;            // number of tied (==T) elements to admit

    // exclusive index-ordered prefix of tie counts (2-level scan)
    int ct = 0;
    for (int j = 0; j < items; ++j) ct += (su[tid * items + j] == T) ? 1 : 0;
    int scan = ct;
    #pragma unroll
    for (int off = 1; off < 32; off <<= 1) {
        int t = __shfl_up_sync(0xffffffffu, scan, off);
        if (lane >= off) scan += t;
    }
    if (lane == 31) warp_agg[wid] = scan;
    __syncthreads();
    if (wid == 0) {
        int v = warp_agg[lane];
        #pragma unroll
        for (int off = 1; off < 32; off <<= 1) {
            int t = __shfl_up_sync(0xffffffffu, v, off);
            if (lane >= off) v += t;
        }
        warp_agg[lane] = v;
    }
    __syncthreads();
    int excl = (wid > 0 ? warp_agg[wid - 1] : 0) + scan - ct;

    for (int j = 0; j < items; ++j) {
        int i = tid * items + j;
        unsigned u = su[i];
        int mk;
        if (u > T) mk = 1;
        else if (u == T) { mk = (excl < r) ? 1 : 0; excl++; }
        else mk = 0;
        mask[i] = mk;
    }
}

// ---------------- 3: degree counts ----------------
__global__ void k_count() {
    int e = blockIdx.x * blockDim.x + threadIdx.x;
    if (e < NE) {
        atomicAdd(&g_cnt[g_src[e]], 1);
        if (g_dst[e] != g_src[e]) atomicAdd(&g_cnt[g_dst[e]], 1);
    }
}

// ---------------- 4: exclusive scan of counts -> offsets ----------------
__global__ void k_scan() {
    __shared__ int sh[1024];
    int tid = threadIdx.x;
    int own = g_cnt[tid];
    sh[tid] = own;
    __syncthreads();
    int val = own;
    for (int dd = 1; dd < 1024; dd <<= 1) {
        int t = (tid >= dd) ? sh[tid - dd] : 0;
        __syncthreads();
        val += t;
        sh[tid] = val;
        __syncthreads();
    }
    g_off[tid] = val - own;
    if (tid == 1023) g_off[1024] = val;
}

// ---------------- 5: deterministic incidence fill (one thread per node, index order) ----------------
__global__ void k_fill() {
    __shared__ int ss[NE], sd[NE];
    for (int i = threadIdx.x; i < NE; i += blockDim.x) { ss[i] = g_src[i]; sd[i] = g_dst[i]; }
    __syncthreads();
    int node = blockIdx.x * blockDim.x + threadIdx.x;
    if (node >= NN) return;
    int p = g_off[node];
    for (int e = 0; e < NE; ++e) {
        if (ss[e] == node || sd[e] == node) g_inc[p++] = e;
    }
}

// ---------------- 6: masked edge features + endpoint node-feature sums ----------------
__global__ void k_prepare(const float* __restrict__ nf, const float* __restrict__ efi) {
    int e = blockIdx.x;
    int d = threadIdx.x;
    int a = g_src[e], b = g_dst[e];
    int em = g_emask[e] & g_nmask[a] & g_nmask[b];
    g_ef[(size_t)e * D + d] = em ? efi[(size_t)e * D + d] : 0.f;
    g_gs[(size_t)e * D + d] = nf[(size_t)a * D + d] + nf[(size_t)b * D + d];
}

// ---------------- 7: fp32 GEMM body, 128x64 tile, 8x4 microtile, double-buffered ----------------
template <int ACT, bool HAS_ADD>
__device__ __forceinline__ void gemm_body(const float* __restrict__ A,
                                          const float* __restrict__ B,
                                          const float* __restrict__ bias,
                                          const float* __restrict__ add,
                                          float* __restrict__ C) {
    __shared__ float As[2][16 * 132];  // As[k][m], padded pitch 132
    __shared__ float Bs[2][16 * 68];   // Bs[k][n], padded pitch 68
    int tid = threadIdx.x;
    int tx = tid & 15, ty = tid >> 4;  // tx: n/4, ty: m/8
    int m0 = blockIdx.y * 128, n0 = blockIdx.x * 64;

    // global-load mapping (fixed per thread)
    int aIdx0 = tid * 2, aIdx1 = tid * 2 + 1;
    int ar0 = aIdx0 >> 2, ak0 = (aIdx0 & 3) << 2;
    int ar1 = aIdx1 >> 2, ak1 = (aIdx1 & 3) << 2;
    int bk = tid >> 4, bn = (tid & 15) << 2;

    // prologue: tile 0 -> smem[0]
    float4 a0 = *(const float4*)&A[(size_t)(m0 + ar0) * D + ak0];
    float4 a1 = *(const float4*)&A[(size_t)(m0 + ar1) * D + ak1];
    float4 b0 = *(const float4*)&B[(size_t)bk * D + n0 + bn];
    As[0][(ak0 + 0) * 132 + ar0] = a0.x;
    As[0][(ak0 + 1) * 132 + ar0] = a0.y;
    As[0][(ak0 + 2) * 132 + ar0] = a0.z;
    As[0][(ak0 + 3) * 132 + ar0] = a0.w;
    As[0][(ak1 + 0) * 132 + ar1] = a1.x;
    As[0][(ak1 + 1) * 132 + ar1] = a1.y;
    As[0][(ak1 + 2) * 132 + ar1] = a1.z;
    As[0][(ak1 + 3) * 132 + ar1] = a1.w;
    *(float4*)&Bs[0][bk * 68 + bn] = b0;
    __syncthreads();

    float acc[8][4] = {};
    int cur = 0;
    for (int k0 = 0; k0 < D; k0 += 16) {
        float4 na0, na1, nb0;
        bool more = (k0 + 16 < D);
        if (more) {  // register-staged prefetch of next tile
            na0 = *(const float4*)&A[(size_t)(m0 + ar0) * D + k0 + 16 + ak0];
            na1 = *(const float4*)&A[(size_t)(m0 + ar1) * D + k0 + 16 + ak1];
            nb0 = *(const float4*)&B[(size_t)(k0 + 16 + bk) * D + n0 + bn];
        }
        #pragma unroll
        for (int kq = 0; kq < 16; ++kq) {
            float4 av0 = *(const float4*)&As[cur][kq * 132 + ty * 8];
            float4 av1 = *(const float4*)&As[cur][kq * 132 + ty * 8 + 4];
            float4 bv  = *(const float4*)&Bs[cur][kq * 68 + tx * 4];
            float am[8] = {av0.x, av0.y, av0.z, av0.w, av1.x, av1.y, av1.z, av1.w};
            float bm[4] = {bv.x, bv.y, bv.z, bv.w};
            #pragma unroll
            for (int i = 0; i < 8; ++i)
                #pragma unroll
                for (int j = 0; j < 4; ++j) acc[i][j] += am[i] * bm[j];
        }
        if (more) {
            int nxt = cur ^ 1;
            As[nxt][(ak0 + 0) * 132 + ar0] = na0.x;
            As[nxt][(ak0 + 1) * 132 + ar0] = na0.y;
            As[nxt][(ak0 + 2) * 132 + ar0] = na0.z;
            As[nxt][(ak0 + 3) * 132 + ar0] = na0.w;
            As[nxt][(ak1 + 0) * 132 + ar1] = na1.x;
            As[nxt][(ak1 + 1) * 132 + ar1] = na1.y;
            As[nxt][(ak1 + 2) * 132 + ar1] = na1.z;
            As[nxt][(ak1 + 3) * 132 + ar1] = na1.w;
            *(float4*)&Bs[nxt][bk * 68 + bn] = nb0;
            __syncthreads();
            cur = nxt;
        }
    }

    float4 b4 = *(const float4*)&bias[n0 + tx * 4];
    float bb[4] = {b4.x, b4.y, b4.z, b4.w};
    #pragma unroll
    for (int i = 0; i < 8; ++i) {
        int m = m0 + ty * 8 + i;
        float o[4];
        #pragma unroll
        for (int j = 0; j < 4; ++j) {
            float v = acc[i][j] + bb[j];
            if (HAS_ADD) v += add[(size_t)m * D + n0 + tx * 4 + j];
            if (ACT == 1) {  // tanh-gelu (jax default)
                float x = v;
                float t = tanhf(0.7978845608028654f * (x + 0.044715f * x * x * x));
                v = 0.5f * x * (1.0f + t);
            }
            o[j] = v;
        }
        *(float4*)&C[(size_t)m * D + n0 + tx * 4] = *(float4*)o;
    }
}

template <int ACT, int AID, int CID, int ADDID>
__global__ void k_gemm(const float* __restrict__ B, const float* __restrict__ bias) {
    gemm_body<ACT, (ADDID >= 0)>(buf<AID>(), B, bias,
                                 (ADDID >= 0) ? buf<(ADDID >= 0 ? ADDID : 0)>() : nullptr,
                                 buf<CID>());
}

// fused q/k/v: blockIdx.z selects the weight/bias/output triple (same A = g_h)
__global__ void k_gemm_qkv(const float* __restrict__ Wq, const float* __restrict__ bq,
                           const float* __restrict__ Wk, const float* __restrict__ bk,
                           const float* __restrict__ Wv, const float* __restrict__ bv) {
    const float* B;
    const float* bias;
    float* C;
    if (blockIdx.z == 0)      { B = Wq; bias = bq; C = g_q; }
    else if (blockIdx.z == 1) { B = Wk; bias = bk; C = g_k; }
    else                      { B = Wv; bias = bv; C = g_v; }
    gemm_body<0, false>(g_h, B, bias, nullptr, C);
}

// ---------------- 8: sparse masked attention (one block per edge, one warp per head) ----------------
__global__ void k_attn() {
    __shared__ int s_cand[MAXC];
    __shared__ float s_sc[HN][MAXC];
    __shared__ int s_n;
    int e = blockIdx.x;
    int tid = threadIdx.x;
    int h = tid >> 5, lane = tid & 31;
    int a = g_src[e], b = g_dst[e];
    int oa = g_off[a];
    int na = g_off[a + 1] - oa;

    for (int i = tid; i < na; i += 128) s_cand[i] = g_inc[oa + i];

    if (tid < 32) {
        int cnt = na;
        if (b != a) {
            int ob = g_off[b];
            int nb = g_off[b + 1] - ob;
            for (int i0 = 0; i0 < nb; i0 += 32) {
                int i = i0 + lane;
                int f = 0, keep = 0;
                if (i < nb) {
                    f = g_inc[ob + i];
                    keep = (g_src[f] != a && g_dst[f] != a) ? 1 : 0;
                }
                unsigned bal = __ballot_sync(0xffffffffu, keep != 0);
                if (keep) {
                    int pos = cnt + __popc(bal & ((1u << lane) - 1u));
                    if (pos < MAXC) s_cand[pos] = f;
                }
                cnt += __popc(bal);
            }
        }
        if (lane == 0) s_n = (cnt < MAXC) ? cnt : MAXC;
    }
    __syncthreads();
    int nc = s_n;
    int base = e * D + h * DHD;

    float2 q2 = *(const float2*)&g_q[base + lane * 2];

    for (int c = 0; c < nc; ++c) {
        int f = s_cand[c];
        float2 k2 = *(const float2*)&g_k[f * D + h * DHD + lane * 2];
        float s = q2.x * k2.x + q2.y * k2.y;
        #pragma unroll
        for (int o = 16; o; o >>= 1) s += __shfl_xor_sync(0xffffffffu, s, o);
        if (lane == 0) s_sc[h][c] = s * 0.125f;
    }
    __syncwarp();

    float mx = -3.0e38f;
    for (int c = lane; c < nc; c += 32) mx = fmaxf(mx, s_sc[h][c]);
    #pragma unroll
    for (int o = 16; o; o >>= 1) mx = fmaxf(mx, __shfl_xor_sync(0xffffffffu, mx, o));
    float l = 0.f;
    for (int c = lane; c < nc; c += 32) {
        float p = __expf(s_sc[h][c] - mx);
        s_sc[h][c] = p;
        l += p;
    }
    #pragma unroll
    for (int o = 16; o; o >>= 1) l += __shfl_xor_sync(0xffffffffu, l, o);
    __syncwarp();

    float ax = 0.f, ay = 0.f;
    for (int c = 0; c < nc; ++c) {
        float p = s_sc[h][c];
        float2 v2 = *(const float2*)&g_v[s_cand[c] * D + h * DHD + lane * 2];
        ax += p * v2.x;
        ay += p * v2.y;
    }
    float inv = 1.f / l;
    float2 r;
    r.x = ax * inv;
    r.y = ay * inv;
    *(float2*)&g_ao[base + lane * 2] = r;
}

// ---------------- 9: classifier  out = hid @ W2[256x16] + b2 (one warp per row) ----------------
__global__ void k_cls(const float* __restrict__ W2, const float* __restrict__ b2,
                      float* __restrict__ out) {
    int warp = (blockIdx.x * blockDim.x + threadIdx.x) >> 5;
    int lane = threadIdx.x & 31;
    if (warp >= NE) return;
    float x[8];
    #pragma unroll
    for (int i = 0; i < 8; ++i) x[i] = g_hid[(size_t)warp * D + lane + i * 32];
    float res = 0.f;
    #pragma unroll
    for (int c = 0; c < CLS; ++c) {
        float s = 0.f;
        #pragma unroll
        for (int i = 0; i < 8; ++i) s += x[i] * W2[(size_t)(lane + i * 32) * CLS + c];
        #pragma unroll
        for (int o = 16; o; o >>= 1) s += __shfl_xor_sync(0xffffffffu, s, o);
        if (lane == c) res = s + b2[c];
    }
    if (lane < CLS) out[(size_t)warp * CLS + lane] = res;
}

// ---------------- host ----------------
extern "C" void kernel_launch(void* const* d_in, const int* in_sizes, int n_in,
                              void* d_out, int out_size) {
    const float* nf   = (const float*)d_in[0];
    const float* efi  = (const float*)d_in[1];
    const int*   ei   = (const int*)d_in[2];
    const float* Wn_r = (const float*)d_in[3];
    const float* bn_r = (const float*)d_in[4];
    const float* We_r = (const float*)d_in[5];
    const float* be_r = (const float*)d_in[6];
    const float* Wnp  = (const float*)d_in[7];
    const float* bnp  = (const float*)d_in[8];
    const float* Wq   = (const float*)d_in[9];
    const float* bq   = (const float*)d_in[10];
    const float* Wk   = (const float*)d_in[11];
    const float* bk   = (const float*)d_in[12];
    const float* Wv   = (const float*)d_in[13];
    const float* bv   = (const float*)d_in[14];
    const float* Wo   = (const float*)d_in[15];
    const float* bo   = (const float*)d_in[16];
    const float* W1   = (const float*)d_in[17];
    const float* b1   = (const float*)d_in[18];
    const float* W2   = (const float*)d_in[19];
    const float* b2   = (const float*)d_in[20];
    float* out = (float*)d_out;

    k_detect<<<1, 256>>>(ei);
    k_convert<<<(NE + 255) / 256, 256>>>(ei);
    k_scores<<<((NN + NE) * 32 + 255) / 256, 256>>>(nf, efi, Wn_r, bn_r, We_r, be_r);
    k_topk<<<2, 1024>>>();
    k_count<<<(NE + 255) / 256, 256>>>();
    k_scan<<<1, 1024>>>();
    k_fill<<<(NN + 255) / 256, 256>>>();
    k_prepare<<<NE, 256>>>(nf, efi);

    dim3 gg(D / 64, NE / 128);      // (4, 32)
    dim3 gq(D / 64, NE / 128, 3);   // fused q/k/v
    // h = gs @ Wnp + bnp + ef
    k_gemm<0, 0, 2, 1><<<gg, 256>>>(Wnp, bnp);
    // q, k, v in one launch
    k_gemm_qkv<<<gq, 256>>>(Wq, bq, Wk, bk, Wv, bv);
    // attention
    k_attn<<<NE, 128>>>();
    // o = ao @ Wo + bo
    k_gemm<0, 6, 7, -1><<<gg, 256>>>(Wo, bo);
    // hid = gelu(o @ W1 + b1)
    k_gemm<1, 7, 8, -1><<<gg, 256>>>(W1, b1);
    // out = hid @ W2 + b2
    k_cls<<<(NE * 32 + 255) / 256, 256>>>(W2, b2, out);
}

// round 6
// speedup vs baseline: 2.6818x; 2.2244x over previous
#include <cuda_runtime.h>
#include <cuda_bf16.h>
#include <math.h>
#include <stdint.h>

#define NN    1024
#define NE    4096
#define D     256
#define HN    4
#define DHD   64
#define NODEK 512
#define EDGEK 2048
#define CLS   16
#define MAXC  1024

// mma.sync GEMM tile: CTA 128x64, K=256 resident, 8 warps (4m x 2n), warp 32x32
#define APITCH 264   // bf16 elements per A row (256 + 8 pad) -> 132 words, stride 4 banks
#define BPITCH 264
// smem (bf16 elements): Ahi[128*264] Alo[...] Bhi[64*264] Blo[...]
#define OFF_AHI 0
#define OFF_ALO (128 * APITCH)
#define OFF_BHI (2 * 128 * APITCH)
#define OFF_BLO (2 * 128 * APITCH + 64 * BPITCH)
#define MMA_SMEM_ELEMS (2 * 128 * APITCH + 2 * 64 * BPITCH)
#define MMA_SMEM_BYTES (MMA_SMEM_ELEMS * 2)

// ---------------- scratch ----------------
__device__ int   g_is64;
__device__ float g_nscore[NN];
__device__ float g_escore[NE];
__device__ int   g_nmask[NN];
__device__ int   g_emask[NE];
__device__ int   g_src[NE], g_dst[NE];
__device__ int   g_cnt[NN];
__device__ int   g_off[NN + 1];
__device__ int   g_pos[NN];
__device__ int   g_inc[2 * NE];
__device__ float g_gs[NE * D];   // 0
__device__ float g_ef[NE * D];   // 1
__device__ float g_h[NE * D];    // 2
__device__ float g_q[NE * D];    // 3
__device__ float g_k[NE * D];    // 4
__device__ float g_v[NE * D];    // 5
__device__ float g_ao[NE * D];   // 6
__device__ float g_o[NE * D];    // 7
__device__ float g_hid[NE * D];  // 8

template <int ID> __device__ __forceinline__ float* buf();
template <> __device__ __forceinline__ float* buf<0>() { return g_gs; }
template <> __device__ __forceinline__ float* buf<1>() { return g_ef; }
template <> __device__ __forceinline__ float* buf<2>() { return g_h; }
template <> __device__ __forceinline__ float* buf<3>() { return g_q; }
template <> __device__ __forceinline__ float* buf<4>() { return g_k; }
template <> __device__ __forceinline__ float* buf<5>() { return g_v; }
template <> __device__ __forceinline__ float* buf<6>() { return g_ao; }
template <> __device__ __forceinline__ float* buf<7>() { return g_o; }
template <> __device__ __forceinline__ float* buf<8>() { return g_hid; }

// ---------------- -1: detect edge_index dtype + zero counts ----------------
__global__ void k_detect(const int* __restrict__ p) {
    __shared__ int sh[256];
    int t = threadIdx.x;
    int acc = 0;
    for (int i = t; i < 2048; i += 256) acc |= p[2 * i + 1];
    sh[t] = acc;
    __syncthreads();
    for (int s = 128; s > 0; s >>= 1) {
        if (t < s) sh[t] |= sh[t + s];
        __syncthreads();
    }
    if (t == 0) g_is64 = (sh[0] == 0) ? 1 : 0;
    for (int i = t; i < NN; i += 256) g_cnt[i] = 0;
}

// ---------------- 0: convert edge_index + degree counts ----------------
__global__ void k_convert(const int* __restrict__ p) {
    int i = blockIdx.x * blockDim.x + threadIdx.x;
    if (i < NE) {
        int s, d;
        if (g_is64) { s = p[2 * i]; d = p[2 * (NE + i)]; }
        else        { s = p[i];     d = p[NE + i]; }
        g_src[i] = s;
        g_dst[i] = d;
        atomicAdd(&g_cnt[s], 1);
        if (d != s) atomicAdd(&g_cnt[d], 1);
    }
}

// ---------------- 1: router scores (one warp per row) ----------------
__global__ void k_scores(const float* __restrict__ nf, const float* __restrict__ ef,
                         const float* __restrict__ Wn, const float* __restrict__ bn,
                         const float* __restrict__ We, const float* __restrict__ be) {
    int warp = (blockIdx.x * blockDim.x + threadIdx.x) >> 5;
    int lane = threadIdx.x & 31;
    if (warp >= NN + NE) return;
    const float* x;
    const float* w;
    if (warp < NN) { x = nf + (size_t)warp * D; w = Wn; }
    else           { x = ef + (size_t)(warp - NN) * D; w = We; }
    float s = 0.f;
    #pragma unroll
    for (int i = 0; i < D / 32; ++i) s += x[lane + i * 32] * w[lane + i * 32];
    #pragma unroll
    for (int o = 16; o; o >>= 1) s += __shfl_xor_sync(0xffffffffu, s, o);
    if (lane == 0) {
        if (warp < NN) g_nscore[warp] = s + bn[0];
        else           g_escore[warp - NN] = s + be[0];
    }
}

// ---------------- 2: exact top-k via 4-pass MSB radix select ----------------
__global__ void k_topk() {
    const bool is_edge = (blockIdx.x == 1);
    const float* sc = is_edge ? g_escore : g_nscore;
    int* mask = is_edge ? g_emask : g_nmask;
    const int n = is_edge ? NE : NN;
    const int kk = is_edge ? EDGEK : NODEK;

    __shared__ unsigned su[NE];
    __shared__ int hist[256];
    __shared__ unsigned sh_pref;
    __shared__ int sh_krem;
    __shared__ int warp_agg[32];

    int tid = threadIdx.x;
    int lane = tid & 31, wid = tid >> 5;
    int items = n >> 10;

    for (int j = 0; j < items; ++j) {
        int i = tid * items + j;
        unsigned b = __float_as_uint(sc[i]);
        su[i] = (b & 0x80000000u) ? ~b : (b | 0x80000000u);
    }
    if (tid == 0) { sh_pref = 0u; sh_krem = kk; }
    __syncthreads();

    for (int shift = 24; shift >= 0; shift -= 8) {
        unsigned prefix = sh_pref;
        unsigned done_mask = (shift == 24) ? 0u : (0xFFFFFFFFu << (shift + 8));
        if (tid < 256) hist[tid] = 0;
        __syncthreads();
        for (int j = 0; j < items; ++j) {
            unsigned u = su[tid * items + j];
            if ((u & done_mask) == prefix)
                atomicAdd(&hist[(u >> shift) & 255], 1);
        }
        __syncthreads();
        if (wid == 0) {
            int krem = sh_krem;
            int gsum = 0;
            #pragma unroll
            for (int c = 0; c < 8; ++c) gsum += hist[lane * 8 + c];
            int x = gsum;
            #pragma unroll
            for (int off = 1; off < 32; off <<= 1) {
                int t = __shfl_down_sync(0xffffffffu, x, off);
                if (lane + off < 32) x += t;
            }
            int above = x - gsum;
            bool hit = (above < krem) && (x >= krem);
            unsigned bal = __ballot_sync(0xffffffffu, hit);
            int srcl = __ffs(bal) - 1;
            if (lane == srcl) {
                int cum = above;
                #pragma unroll
                for (int c = 7; c >= 0; --c) {
                    int b = lane * 8 + c;
                    int hc = hist[b];
                    if (cum + hc >= krem) {
                        sh_pref = prefix | ((unsigned)b << shift);
                        sh_krem = krem - cum;
                        break;
                    }
                    cum += hc;
                }
            }
        }
        __syncthreads();
    }
    unsigned T = sh_pref;
    int r = sh_krem;

    int ct = 0;
    for (int j = 0; j < items; ++j) ct += (su[tid * items + j] == T) ? 1 : 0;
    int scan = ct;
    #pragma unroll
    for (int off = 1; off < 32; off <<= 1) {
        int t = __shfl_up_sync(0xffffffffu, scan, off);
        if (lane >= off) scan += t;
    }
    if (lane == 31) warp_agg[wid] = scan;
    __syncthreads();
    if (wid == 0) {
        int v = warp_agg[lane];
        #pragma unroll
        for (int off = 1; off < 32; off <<= 1) {
            int t = __shfl_up_sync(0xffffffffu, v, off);
            if (lane >= off) v += t;
        }
        warp_agg[lane] = v;
    }
    __syncthreads();
    int excl = (wid > 0 ? warp_agg[wid - 1] : 0) + scan - ct;

    for (int j = 0; j < items; ++j) {
        int i = tid * items + j;
        unsigned u = su[i];
        int mk;
        if (u > T) mk = 1;
        else if (u == T) { mk = (excl < r) ? 1 : 0; excl++; }
        else mk = 0;
        mask[i] = mk;
    }
}

// ---------------- 4: scan counts -> offsets (+ pos copy) ----------------
__global__ void k_scan() {
    __shared__ int sh[1024];
    int tid = threadIdx.x;
    int own = g_cnt[tid];
    sh[tid] = own;
    __syncthreads();
    int val = own;
    for (int dd = 1; dd < 1024; dd <<= 1) {
        int t = (tid >= dd) ? sh[tid - dd] : 0;
        __syncthreads();
        val += t;
        sh[tid] = val;
        __syncthreads();
    }
    g_off[tid] = val - own;
    g_pos[tid] = val - own;
    if (tid == 1023) g_off[1024] = val;
}

// ---------------- 5a: atomic incidence fill (unordered) ----------------
__global__ void k_fill_at() {
    int e = blockIdx.x * blockDim.x + threadIdx.x;
    if (e < NE) {
        int a = g_src[e], b = g_dst[e];
        g_inc[atomicAdd(&g_pos[a], 1)] = e;
        if (b != a) g_inc[atomicAdd(&g_pos[b], 1)] = e;
    }
}

// ---------------- 5b: per-node insertion sort -> deterministic index order ----------------
__global__ void k_sortinc() {
    int node = blockIdx.x * blockDim.x + threadIdx.x;
    if (node >= NN) return;
    int s = g_off[node], t = g_off[node + 1];
    for (int i = s + 1; i < t; ++i) {
        int v = g_inc[i];
        int j = i - 1;
        while (j >= s && g_inc[j] > v) { g_inc[j + 1] = g_inc[j]; --j; }
        g_inc[j + 1] = v;
    }
}

// ---------------- 6: masked edge features + endpoint node-feature sums ----------------
__global__ void k_prepare(const float* __restrict__ nf, const float* __restrict__ efi) {
    int e = blockIdx.x;
    int d = threadIdx.x;
    int a = g_src[e], b = g_dst[e];
    int em = g_emask[e] & g_nmask[a] & g_nmask[b];
    g_ef[(size_t)e * D + d] = em ? efi[(size_t)e * D + d] : 0.f;
    g_gs[(size_t)e * D + d] = nf[(size_t)a * D + d] + nf[(size_t)b * D + d];
}

// ---------------- 7: split-bf16 tensor-core GEMM via mma.sync (compute_103-legal) ----------------
// C[m][n] = sum_k A[m][k]*W[k][n] (+bias)(+add)(+gelu)
// A*W ~= Ahi*Whi + Ahi*Wlo + Alo*Whi, fp32 accum (error ~2^-16 relative).
__device__ __forceinline__ void mma_bf16(float* c, const uint32_t* a, const uint32_t* b) {
    asm volatile(
        "mma.sync.aligned.m16n8k16.row.col.f32.bf16.bf16.f32 "
        "{%0,%1,%2,%3}, {%4,%5,%6,%7}, {%8,%9}, {%0,%1,%2,%3};"
        : "+f"(c[0]), "+f"(c[1]), "+f"(c[2]), "+f"(c[3])
        : "r"(a[0]), "r"(a[1]), "r"(a[2]), "r"(a[3]), "r"(b[0]), "r"(b[1]));
}

template <int ACT, bool HAS_ADD>
__device__ __forceinline__ void gemm_mma_body(const float* __restrict__ A,
                                              const float* __restrict__ W,
                                              const float* __restrict__ bias,
                                              const float* __restrict__ add,
                                              float* __restrict__ C) {
    extern __shared__ __nv_bfloat16 sm[];
    __nv_bfloat16* as_hi = sm + OFF_AHI;
    __nv_bfloat16* as_lo = sm + OFF_ALO;
    __nv_bfloat16* bs_hi = sm + OFF_BHI;
    __nv_bfloat16* bs_lo = sm + OFF_BLO;

    int tid = threadIdx.x;
    int wid = tid >> 5, lane = tid & 31;
    int g = lane >> 2, t = lane & 3;        // mma fragment coords
    int wm = wid >> 1, wn = wid & 1;        // warp grid 4m x 2n
    int m0 = blockIdx.y * 128, n0 = blockIdx.x * 64;

    // ---- load + split-convert A: 128 x 256 (float4 -> bf16 hi/lo) ----
    #pragma unroll
    for (int it = 0; it < 32; ++it) {
        int idx = it * 256 + tid;           // 8192 float4 total
        int m = idx >> 6, k4 = (idx & 63) * 4;
        float4 a = *(const float4*)&A[(size_t)(m0 + m) * D + k4];
        __nv_bfloat16 h0 = __float2bfloat16(a.x), h1 = __float2bfloat16(a.y);
        __nv_bfloat16 h2 = __float2bfloat16(a.z), h3 = __float2bfloat16(a.w);
        __nv_bfloat16 l0 = __float2bfloat16(a.x - __bfloat162float(h0));
        __nv_bfloat16 l1 = __float2bfloat16(a.y - __bfloat162float(h1));
        __nv_bfloat16 l2 = __float2bfloat16(a.z - __bfloat162float(h2));
        __nv_bfloat16 l3 = __float2bfloat16(a.w - __bfloat162float(h3));
        int o = m * APITCH + k4;
        *(__nv_bfloat162*)&as_hi[o]     = __nv_bfloat162(h0, h1);
        *(__nv_bfloat162*)&as_hi[o + 2] = __nv_bfloat162(h2, h3);
        *(__nv_bfloat162*)&as_lo[o]     = __nv_bfloat162(l0, l1);
        *(__nv_bfloat162*)&as_lo[o + 2] = __nv_bfloat162(l2, l3);
    }
    // ---- load + split-convert + transpose B: bs[n][k] = W[k][n0+n], 64 x 256 ----
    {
        int n4 = (tid & 15) * 4;
        for (int k = tid >> 4; k < D; k += 16) {
            float4 w = *(const float4*)&W[(size_t)k * D + n0 + n4];
            float wv[4] = {w.x, w.y, w.z, w.w};
            #pragma unroll
            for (int j = 0; j < 4; ++j) {
                __nv_bfloat16 hi = __float2bfloat16(wv[j]);
                __nv_bfloat16 lo = __float2bfloat16(wv[j] - __bfloat162float(hi));
                bs_hi[(n4 + j) * BPITCH + k] = hi;
                bs_lo[(n4 + j) * BPITCH + k] = lo;
            }
        }
    }
    __syncthreads();

    float acc[2][4][4] = {};
    // ---- 16 k-steps of m16n8k16, 3 split terms each ----
    #pragma unroll 4
    for (int ks = 0; ks < 16; ++ks) {
        int kb = ks * 16;
        uint32_t ah[2][4], al[2][4], bh[4][2], bl[4][2];
        #pragma unroll
        for (int mf = 0; mf < 2; ++mf) {
            int r = wm * 32 + mf * 16 + g;
            int o0 = r * APITCH + kb + 2 * t;
            int o1 = (r + 8) * APITCH + kb + 2 * t;
            ah[mf][0] = *(const uint32_t*)&as_hi[o0];
            ah[mf][1] = *(const uint32_t*)&as_hi[o1];
            ah[mf][2] = *(const uint32_t*)&as_hi[o0 + 8];
            ah[mf][3] = *(const uint32_t*)&as_hi[o1 + 8];
            al[mf][0] = *(const uint32_t*)&as_lo[o0];
            al[mf][1] = *(const uint32_t*)&as_lo[o1];
            al[mf][2] = *(const uint32_t*)&as_lo[o0 + 8];
            al[mf][3] = *(const uint32_t*)&as_lo[o1 + 8];
        }
        #pragma unroll
        for (int nf = 0; nf < 4; ++nf) {
            int r = wn * 32 + nf * 8 + g;
            int o = r * BPITCH + kb + 2 * t;
            bh[nf][0] = *(const uint32_t*)&bs_hi[o];
            bh[nf][1] = *(const uint32_t*)&bs_hi[o + 8];
            bl[nf][0] = *(const uint32_t*)&bs_lo[o];
            bl[nf][1] = *(const uint32_t*)&bs_lo[o + 8];
        }
        #pragma unroll
        for (int mf = 0; mf < 2; ++mf)
            #pragma unroll
            for (int nf = 0; nf < 4; ++nf) {
                mma_bf16(acc[mf][nf], ah[mf], bh[nf]);
                mma_bf16(acc[mf][nf], ah[mf], bl[nf]);
                mma_bf16(acc[mf][nf], al[mf], bh[nf]);
            }
    }

    // ---- epilogue: fragment layout c0,c1 = C[g][2t..], c2,c3 = C[g+8][2t..] ----
    #pragma unroll
    for (int mf = 0; mf < 2; ++mf) {
        int r0 = m0 + wm * 32 + mf * 16 + g;
        #pragma unroll
        for (int nf = 0; nf < 4; ++nf) {
            int c = n0 + wn * 32 + nf * 8 + 2 * t;
            float bb0 = bias[c], bb1 = bias[c + 1];
            #pragma unroll
            for (int half = 0; half < 2; ++half) {
                int r = r0 + half * 8;
                float v0 = acc[mf][nf][half * 2 + 0] + bb0;
                float v1 = acc[mf][nf][half * 2 + 1] + bb1;
                if (HAS_ADD) {
                    v0 += add[(size_t)r * D + c];
                    v1 += add[(size_t)r * D + c + 1];
                }
                if (ACT == 1) {
                    float x0 = v0, x1 = v1;
                    float t0 = tanhf(0.7978845608028654f * (x0 + 0.044715f * x0 * x0 * x0));
                    float t1 = tanhf(0.7978845608028654f * (x1 + 0.044715f * x1 * x1 * x1));
                    v0 = 0.5f * x0 * (1.0f + t0);
                    v1 = 0.5f * x1 * (1.0f + t1);
                }
                float2 o2 = {v0, v1};
                *(float2*)&C[(size_t)r * D + c] = o2;
            }
        }
    }
}

template <int ACT, int AID, int CID, int ADDID>
__global__ void __launch_bounds__(256, 1) k_gemm_mma(const float* __restrict__ W,
                                                     const float* __restrict__ bias) {
    gemm_mma_body<ACT, (ADDID >= 0)>(buf<AID>(), W, bias,
                                     (ADDID >= 0) ? buf<(ADDID >= 0 ? ADDID : 0)>() : nullptr,
                                     buf<CID>());
}

__global__ void __launch_bounds__(256, 1) k_gemm_mma_qkv(
        const float* __restrict__ Wq, const float* __restrict__ bq,
        const float* __restrict__ Wk, const float* __restrict__ bk,
        const float* __restrict__ Wv, const float* __restrict__ bv) {
    const float* W;
    const float* bias;
    float* C;
    if (blockIdx.z == 0)      { W = Wq; bias = bq; C = g_q; }
    else if (blockIdx.z == 1) { W = Wk; bias = bk; C = g_k; }
    else                      { W = Wv; bias = bv; C = g_v; }
    gemm_mma_body<0, false>(g_h, W, bias, nullptr, C);
}

// ---------------- 8: sparse masked attention ----------------
__global__ void k_attn() {
    __shared__ int s_cand[MAXC];
    __shared__ float s_sc[HN][MAXC];
    __shared__ int s_n;
    int e = blockIdx.x;
    int tid = threadIdx.x;
    int h = tid >> 5, lane = tid & 31;
    int a = g_src[e], b = g_dst[e];
    int oa = g_off[a];
    int na = g_off[a + 1] - oa;

    for (int i = tid; i < na; i += 128) s_cand[i] = g_inc[oa + i];

    if (tid < 32) {
        int cnt = na;
        if (b != a) {
            int ob = g_off[b];
            int nb = g_off[b + 1] - ob;
            for (int i0 = 0; i0 < nb; i0 += 32) {
                int i = i0 + lane;
                int f = 0, keep = 0;
                if (i < nb) {
                    f = g_inc[ob + i];
                    keep = (g_src[f] != a && g_dst[f] != a) ? 1 : 0;
                }
                unsigned bal = __ballot_sync(0xffffffffu, keep != 0);
                if (keep) {
                    int pos = cnt + __popc(bal & ((1u << lane) - 1u));
                    if (pos < MAXC) s_cand[pos] = f;
                }
                cnt += __popc(bal);
            }
        }
        if (lane == 0) s_n = (cnt < MAXC) ? cnt : MAXC;
    }
    __syncthreads();
    int nc = s_n;
    int base = e * D + h * DHD;

    float2 q2 = *(const float2*)&g_q[base + lane * 2];

    for (int c = 0; c < nc; ++c) {
        int f = s_cand[c];
        float2 k2 = *(const float2*)&g_k[f * D + h * DHD + lane * 2];
        float s = q2.x * k2.x + q2.y * k2.y;
        #pragma unroll
        for (int o = 16; o; o >>= 1) s += __shfl_xor_sync(0xffffffffu, s, o);
        if (lane == 0) s_sc[h][c] = s * 0.125f;
    }
    __syncwarp();

    float mx = -3.0e38f;
    for (int c = lane; c < nc; c += 32) mx = fmaxf(mx, s_sc[h][c]);
    #pragma unroll
    for (int o = 16; o; o >>= 1) mx = fmaxf(mx, __shfl_xor_sync(0xffffffffu, mx, o));
    float l = 0.f;
    for (int c = lane; c < nc; c += 32) {
        float p = __expf(s_sc[h][c] - mx);
        s_sc[h][c] = p;
        l += p;
    }
    #pragma unroll
    for (int o = 16; o; o >>= 1) l += __shfl_xor_sync(0xffffffffu, l, o);
    __syncwarp();

    float ax = 0.f, ay = 0.f;
    for (int c = 0; c < nc; ++c) {
        float p = s_sc[h][c];
        float2 v2 = *(const float2*)&g_v[s_cand[c] * D + h * DHD + lane * 2];
        ax += p * v2.x;
        ay += p * v2.y;
    }
    float inv = 1.f / l;
    float2 r;
    r.x = ax * inv;
    r.y = ay * inv;
    *(float2*)&g_ao[base + lane * 2] = r;
}

// ---------------- 9: classifier ----------------
__global__ void k_cls(const float* __restrict__ W2, const float* __restrict__ b2,
                      float* __restrict__ out) {
    int warp = (blockIdx.x * blockDim.x + threadIdx.x) >> 5;
    int lane = threadIdx.x & 31;
    if (warp >= NE) return;
    float x[8];
    #pragma unroll
    for (int i = 0; i < 8; ++i) x[i] = g_hid[(size_t)warp * D + lane + i * 32];
    float res = 0.f;
    #pragma unroll
    for (int c = 0; c < CLS; ++c) {
        float s = 0.f;
        #pragma unroll
        for (int i = 0; i < 8; ++i) s += x[i] * W2[(size_t)(lane + i * 32) * CLS + c];
        #pragma unroll
        for (int o = 16; o; o >>= 1) s += __shfl_xor_sync(0xffffffffu, s, o);
        if (lane == c) res = s + b2[c];
    }
    if (lane < CLS) out[(size_t)warp * CLS + lane] = res;
}

// ---------------- host ----------------
extern "C" void kernel_launch(void* const* d_in, const int* in_sizes, int n_in,
                              void* d_out, int out_size) {
    const float* nf   = (const float*)d_in[0];
    const float* efi  = (const float*)d_in[1];
    const int*   ei   = (const int*)d_in[2];
    const float* Wn_r = (const float*)d_in[3];
    const float* bn_r = (const float*)d_in[4];
    const float* We_r = (const float*)d_in[5];
    const float* be_r = (const float*)d_in[6];
    const float* Wnp  = (const float*)d_in[7];
    const float* bnp  = (const float*)d_in[8];
    const float* Wq   = (const float*)d_in[9];
    const float* bq   = (const float*)d_in[10];
    const float* Wk   = (const float*)d_in[11];
    const float* bk   = (const float*)d_in[12];
    const float* Wv   = (const float*)d_in[13];
    const float* bv   = (const float*)d_in[14];
    const float* Wo   = (const float*)d_in[15];
    const float* bo   = (const float*)d_in[16];
    const float* W1   = (const float*)d_in[17];
    const float* b1   = (const float*)d_in[18];
    const float* W2   = (const float*)d_in[19];
    const float* b2   = (const float*)d_in[20];
    float* out = (float*)d_out;

    // opt-in to large dynamic smem (host-side attribute, no allocation)
    cudaFuncSetAttribute(k_gemm_mma<0, 0, 2, 1>, cudaFuncAttributeMaxDynamicSharedMemorySize, MMA_SMEM_BYTES);
    cudaFuncSetAttribute(k_gemm_mma_qkv, cudaFuncAttributeMaxDynamicSharedMemorySize, MMA_SMEM_BYTES);
    cudaFuncSetAttribute(k_gemm_mma<0, 6, 7, -1>, cudaFuncAttributeMaxDynamicSharedMemorySize, MMA_SMEM_BYTES);
    cudaFuncSetAttribute(k_gemm_mma<1, 7, 8, -1>, cudaFuncAttributeMaxDynamicSharedMemorySize, MMA_SMEM_BYTES);

    k_detect<<<1, 256>>>(ei);
    k_convert<<<(NE + 255) / 256, 256>>>(ei);
    k_scores<<<((NN + NE) * 32 + 255) / 256, 256>>>(nf, efi, Wn_r, bn_r, We_r, be_r);
    k_topk<<<2, 1024>>>();
    k_scan<<<1, 1024>>>();
    k_fill_at<<<(NE + 255) / 256, 256>>>();
    k_sortinc<<<(NN + 255) / 256, 256>>>();
    k_prepare<<<NE, 256>>>(nf, efi);

    dim3 gg(D / 64, NE / 128);      // (4, 32)
    dim3 gq(D / 64, NE / 128, 3);   // fused q/k/v
    k_gemm_mma<0, 0, 2, 1><<<gg, 256, MMA_SMEM_BYTES>>>(Wnp, bnp);        // h = gs@Wnp + bnp + ef
    k_gemm_mma_qkv<<<gq, 256, MMA_SMEM_BYTES>>>(Wq, bq, Wk, bk, Wv, bv);  // q,k,v
    k_attn<<<NE, 128>>>();
    k_gemm_mma<0, 6, 7, -1><<<gg, 256, MMA_SMEM_BYTES>>>(Wo, bo);         // o = ao@Wo + bo
    k_gemm_mma<1, 7, 8, -1><<<gg, 256, MMA_SMEM_BYTES>>>(W1, b1);         // hid = gelu(o@W1 + b1)
    k_cls<<<(NE * 32 + 255) / 256, 256>>>(W2, b2, out);
}

// round 7
// speedup vs baseline: 3.0235x; 1.1274x over previous
#include <cuda_runtime.h>
#include <cuda_bf16.h>
#include <math.h>
#include <stdint.h>

#define NN    1024
#define NE    4096
#define D     256
#define HN    4
#define DHD   64
#define NODEK 512
#define EDGEK 2048
#define CLS   16
#define MAXC  1024

// mma.sync GEMM tile: CTA 128x64, K=256 resident, 8 warps (4m x 2n), warp 32x32
#define APITCH 264
#define BPITCH 264
#define OFF_AHI 0
#define OFF_ALO (128 * APITCH)
#define OFF_BHI (2 * 128 * APITCH)
#define OFF_BLO (2 * 128 * APITCH + 64 * BPITCH)
#define MMA_SMEM_ELEMS (2 * 128 * APITCH + 2 * 64 * BPITCH)
#define MMA_SMEM_BYTES (MMA_SMEM_ELEMS * 2)

// ---------------- scratch ----------------
__device__ float g_nscore[NN];
__device__ float g_escore[NE];
__device__ int   g_nmask[NN];
__device__ int   g_emask[NE];
__device__ int   g_src[NE], g_dst[NE];
__device__ int   g_cnt[NN];
__device__ int   g_off[NN + 1];
__device__ int   g_pos[NN];
__device__ int   g_inc[2 * NE];
__device__ float g_gs[NE * D];   // 0
__device__ float g_ef[NE * D];   // 1
__device__ float g_h[NE * D];    // 2
__device__ float g_q[NE * D];    // 3
__device__ float g_k[NE * D];    // 4
__device__ float g_v[NE * D];    // 5
__device__ float g_ao[NE * D];   // 6
__device__ float g_o[NE * D];    // 7
__device__ float g_hid[NE * D];  // 8
// transposed split-bf16 weights: [w][n][k], w: 0=Wnp 1=Wq 2=Wk 3=Wv 4=Wo 5=W1
__device__ __nv_bfloat16 g_wthi[6 * D * D];
__device__ __nv_bfloat16 g_wtlo[6 * D * D];

template <int ID> __device__ __forceinline__ float* buf();
template <> __device__ __forceinline__ float* buf<0>() { return g_gs; }
template <> __device__ __forceinline__ float* buf<1>() { return g_ef; }
template <> __device__ __forceinline__ float* buf<2>() { return g_h; }
template <> __device__ __forceinline__ float* buf<3>() { return g_q; }
template <> __device__ __forceinline__ float* buf<4>() { return g_k; }
template <> __device__ __forceinline__ float* buf<5>() { return g_v; }
template <> __device__ __forceinline__ float* buf<6>() { return g_ao; }
template <> __device__ __forceinline__ float* buf<7>() { return g_o; }
template <> __device__ __forceinline__ float* buf<8>() { return g_hid; }

// ---------------- P: weight prep — split-bf16 + transpose, 64x64 smem tiles ----------------
// grid (4, 4, 6): x = n tile, y = k tile, z = weight. Also zeroes g_cnt (block 0).
__global__ void k_prepw(const float* __restrict__ Wnp, const float* __restrict__ Wq,
                        const float* __restrict__ Wk, const float* __restrict__ Wv,
                        const float* __restrict__ Wo, const float* __restrict__ W1) {
    __shared__ float s[64][65];
    int w = blockIdx.z;
    const float* W;
    switch (w) {
        case 0: W = Wnp; break;
        case 1: W = Wq; break;
        case 2: W = Wk; break;
        case 3: W = Wv; break;
        case 4: W = Wo; break;
        default: W = W1; break;
    }
    int t = threadIdx.x;
    if (blockIdx.x == 0 && blockIdx.y == 0 && w == 0) {
        #pragma unroll
        for (int i = 0; i < 4; ++i) g_cnt[t + i * 256] = 0;
    }
    int k0 = blockIdx.y * 64, n0 = blockIdx.x * 64;
    int n4 = (t & 15) * 4, kr = t >> 4;
    #pragma unroll
    for (int kk = kr; kk < 64; kk += 16) {
        float4 v = *(const float4*)&W[(size_t)(k0 + kk) * D + n0 + n4];
        s[kk][n4] = v.x;
        s[kk][n4 + 1] = v.y;
        s[kk][n4 + 2] = v.z;
        s[kk][n4 + 3] = v.w;
    }
    __syncthreads();
    // output: thread covers one n row chunk of 16 k
    int nl = t >> 2, kq = (t & 3) * 16;
    __nv_bfloat16 hi[16], lo[16];
    #pragma unroll
    for (int i = 0; i < 16; ++i) {
        float x = s[kq + i][nl];
        hi[i] = __float2bfloat16(x);
        lo[i] = __float2bfloat16(x - __bfloat162float(hi[i]));
    }
    size_t off = (size_t)w * D * D + (size_t)(n0 + nl) * D + k0 + kq;
    *(uint4*)&g_wthi[off] = *(uint4*)&hi[0];
    *(uint4*)&g_wthi[off + 8] = *(uint4*)&hi[8];
    *(uint4*)&g_wtlo[off] = *(uint4*)&lo[0];
    *(uint4*)&g_wtlo[off + 8] = *(uint4*)&lo[8];
}

// ---------------- 0: convert edge_index (self-detecting dtype) + degree counts ----------------
__global__ void k_convert(const int* __restrict__ p) {
    __shared__ int sh[256];
    int t = threadIdx.x;
    int acc = 0;
    for (int i = t; i < 2048; i += 256) acc |= p[2 * i + 1];
    sh[t] = acc;
    __syncthreads();
    for (int s = 128; s > 0; s >>= 1) {
        if (t < s) sh[t] |= sh[t + s];
        __syncthreads();
    }
    int is64 = (sh[0] == 0) ? 1 : 0;  // int64 iff all high words of first 2048 pairs are 0
    int i = blockIdx.x * 256 + t;
    if (i < NE) {
        int s, d;
        if (is64) { s = p[2 * i]; d = p[2 * (NE + i)]; }
        else      { s = p[i];     d = p[NE + i]; }
        g_src[i] = s;
        g_dst[i] = d;
        atomicAdd(&g_cnt[s], 1);
        if (d != s) atomicAdd(&g_cnt[d], 1);
    }
}

// ---------------- 1: router scores (one warp per row) ----------------
__global__ void k_scores(const float* __restrict__ nf, const float* __restrict__ ef,
                         const float* __restrict__ Wn, const float* __restrict__ bn,
                         const float* __restrict__ We, const float* __restrict__ be) {
    int warp = (blockIdx.x * blockDim.x + threadIdx.x) >> 5;
    int lane = threadIdx.x & 31;
    if (warp >= NN + NE) return;
    const float* x;
    const float* w;
    if (warp < NN) { x = nf + (size_t)warp * D; w = Wn; }
    else           { x = ef + (size_t)(warp - NN) * D; w = We; }
    float s = 0.f;
    #pragma unroll
    for (int i = 0; i < D / 32; ++i) s += x[lane + i * 32] * w[lane + i * 32];
    #pragma unroll
    for (int o = 16; o; o >>= 1) s += __shfl_xor_sync(0xffffffffu, s, o);
    if (lane == 0) {
        if (warp < NN) g_nscore[warp] = s + bn[0];
        else           g_escore[warp - NN] = s + be[0];
    }
}

// ---------------- 2: exact top-k via 4-pass MSB radix select ----------------
__global__ void k_topk() {
    const bool is_edge = (blockIdx.x == 1);
    const float* sc = is_edge ? g_escore : g_nscore;
    int* mask = is_edge ? g_emask : g_nmask;
    const int n = is_edge ? NE : NN;
    const int kk = is_edge ? EDGEK : NODEK;

    __shared__ unsigned su[NE];
    __shared__ int hist[256];
    __shared__ unsigned sh_pref;
    __shared__ int sh_krem;
    __shared__ int warp_agg[32];

    int tid = threadIdx.x;
    int lane = tid & 31, wid = tid >> 5;
    int items = n >> 10;

    for (int j = 0; j < items; ++j) {
        int i = tid * items + j;
        unsigned b = __float_as_uint(sc[i]);
        su[i] = (b & 0x80000000u) ? ~b : (b | 0x80000000u);
    }
    if (tid == 0) { sh_pref = 0u; sh_krem = kk; }
    __syncthreads();

    for (int shift = 24; shift >= 0; shift -= 8) {
        unsigned prefix = sh_pref;
        unsigned done_mask = (shift == 24) ? 0u : (0xFFFFFFFFu << (shift + 8));
        if (tid < 256) hist[tid] = 0;
        __syncthreads();
        for (int j = 0; j < items; ++j) {
            unsigned u = su[tid * items + j];
            if ((u & done_mask) == prefix)
                atomicAdd(&hist[(u >> shift) & 255], 1);
        }
        __syncthreads();
        if (wid == 0) {
            int krem = sh_krem;
            int gsum = 0;
            #pragma unroll
            for (int c = 0; c < 8; ++c) gsum += hist[lane * 8 + c];
            int x = gsum;
            #pragma unroll
            for (int off = 1; off < 32; off <<= 1) {
                int t = __shfl_down_sync(0xffffffffu, x, off);
                if (lane + off < 32) x += t;
            }
            int above = x - gsum;
            bool hit = (above < krem) && (x >= krem);
            unsigned bal = __ballot_sync(0xffffffffu, hit);
            int srcl = __ffs(bal) - 1;
            if (lane == srcl) {
                int cum = above;
                #pragma unroll
                for (int c = 7; c >= 0; --c) {
                    int b = lane * 8 + c;
                    int hc = hist[b];
                    if (cum + hc >= krem) {
                        sh_pref = prefix | ((unsigned)b << shift);
                        sh_krem = krem - cum;
                        break;
                    }
                    cum += hc;
                }
            }
        }
        __syncthreads();
    }
    unsigned T = sh_pref;
    int r = sh_krem;

    int ct = 0;
    for (int j = 0; j < items; ++j) ct += (su[tid * items + j] == T) ? 1 : 0;
    int scan = ct;
    #pragma unroll
    for (int off = 1; off < 32; off <<= 1) {
        int t = __shfl_up_sync(0xffffffffu, scan, off);
        if (lane >= off) scan += t;
    }
    if (lane == 31) warp_agg[wid] = scan;
    __syncthreads();
    if (wid == 0) {
        int v = warp_agg[lane];
        #pragma unroll
        for (int off = 1; off < 32; off <<= 1) {
            int t = __shfl_up_sync(0xffffffffu, v, off);
            if (lane >= off) v += t;
        }
        warp_agg[lane] = v;
    }
    __syncthreads();
    int excl = (wid > 0 ? warp_agg[wid - 1] : 0) + scan - ct;

    for (int j = 0; j < items; ++j) {
        int i = tid * items + j;
        unsigned u = su[i];
        int mk;
        if (u > T) mk = 1;
        else if (u == T) { mk = (excl < r) ? 1 : 0; excl++; }
        else mk = 0;
        mask[i] = mk;
    }
}

// ---------------- 4: scan counts -> offsets (+ pos copy) ----------------
__global__ void k_scan() {
    __shared__ int sh[1024];
    int tid = threadIdx.x;
    int own = g_cnt[tid];
    sh[tid] = own;
    __syncthreads();
    int val = own;
    for (int dd = 1; dd < 1024; dd <<= 1) {
        int t = (tid >= dd) ? sh[tid - dd] : 0;
        __syncthreads();
        val += t;
        sh[tid] = val;
        __syncthreads();
    }
    g_off[tid] = val - own;
    g_pos[tid] = val - own;
    if (tid == 1023) g_off[1024] = val;
}

// ---------------- 5a: atomic incidence fill (unordered) ----------------
__global__ void k_fill_at() {
    int e = blockIdx.x * blockDim.x + threadIdx.x;
    if (e < NE) {
        int a = g_src[e], b = g_dst[e];
        g_inc[atomicAdd(&g_pos[a], 1)] = e;
        if (b != a) g_inc[atomicAdd(&g_pos[b], 1)] = e;
    }
}

// ---------------- 5b: per-node insertion sort -> deterministic index order ----------------
__global__ void k_sortinc() {
    int node = blockIdx.x * blockDim.x + threadIdx.x;
    if (node >= NN) return;
    int s = g_off[node], t = g_off[node + 1];
    for (int i = s + 1; i < t; ++i) {
        int v = g_inc[i];
        int j = i - 1;
        while (j >= s && g_inc[j] > v) { g_inc[j + 1] = g_inc[j]; --j; }
        g_inc[j + 1] = v;
    }
}

// ---------------- 6: masked edge features + endpoint node-feature sums ----------------
__global__ void k_prepare(const float* __restrict__ nf, const float* __restrict__ efi) {
    int e = blockIdx.x;
    int d = threadIdx.x;
    int a = g_src[e], b = g_dst[e];
    int em = g_emask[e] & g_nmask[a] & g_nmask[b];
    g_ef[(size_t)e * D + d] = em ? efi[(size_t)e * D + d] : 0.f;
    g_gs[(size_t)e * D + d] = nf[(size_t)a * D + d] + nf[(size_t)b * D + d];
}

// ---------------- 7: split-bf16 tensor-core GEMM (weights precomputed/transposed) ----------------
__device__ __forceinline__ void mma_bf16(float* c, const uint32_t* a, const uint32_t* b) {
    asm volatile(
        "mma.sync.aligned.m16n8k16.row.col.f32.bf16.bf16.f32 "
        "{%0,%1,%2,%3}, {%4,%5,%6,%7}, {%8,%9}, {%0,%1,%2,%3};"
        : "+f"(c[0]), "+f"(c[1]), "+f"(c[2]), "+f"(c[3])
        : "r"(a[0]), "r"(a[1]), "r"(a[2]), "r"(a[3]), "r"(b[0]), "r"(b[1]));
}

template <int ACT, bool HAS_ADD>
__device__ __forceinline__ void gemm_mma_body(const float* __restrict__ A, int wslot,
                                              const float* __restrict__ bias,
                                              const float* __restrict__ add,
                                              float* __restrict__ C) {
    extern __shared__ __nv_bfloat16 sm[];
    __nv_bfloat16* as_hi = sm + OFF_AHI;
    __nv_bfloat16* as_lo = sm + OFF_ALO;
    __nv_bfloat16* bs_hi = sm + OFF_BHI;
    __nv_bfloat16* bs_lo = sm + OFF_BLO;

    int tid = threadIdx.x;
    int wid = tid >> 5, lane = tid & 31;
    int g = lane >> 2, t = lane & 3;
    int wm = wid >> 1, wn = wid & 1;
    int m0 = blockIdx.y * 128, n0 = blockIdx.x * 64;

    // ---- B fill: conflict-free uint4 copy of precomputed [n][k] bf16 weights ----
    const __nv_bfloat16* Bh = g_wthi + (size_t)wslot * D * D;
    const __nv_bfloat16* Bl = g_wtlo + (size_t)wslot * D * D;
    #pragma unroll
    for (int it = 0; it < 8; ++it) {
        int idx = it * 256 + tid;            // 2048 uint4 per array
        int n = idx >> 5, kq = (idx & 31) * 8;
        uint4 vh = *(const uint4*)&Bh[(size_t)(n0 + n) * D + kq];
        uint4 vl = *(const uint4*)&Bl[(size_t)(n0 + n) * D + kq];
        *(uint4*)&bs_hi[n * BPITCH + kq] = vh;
        *(uint4*)&bs_lo[n * BPITCH + kq] = vl;
    }

    // ---- A fill: load + split-convert 128 x 256 fp32 ----
    #pragma unroll
    for (int it = 0; it < 32; ++it) {
        int idx = it * 256 + tid;
        int m = idx >> 6, k4 = (idx & 63) * 4;
        float4 a = *(const float4*)&A[(size_t)(m0 + m) * D + k4];
        __nv_bfloat16 h0 = __float2bfloat16(a.x), h1 = __float2bfloat16(a.y);
        __nv_bfloat16 h2 = __float2bfloat16(a.z), h3 = __float2bfloat16(a.w);
        __nv_bfloat16 l0 = __float2bfloat16(a.x - __bfloat162float(h0));
        __nv_bfloat16 l1 = __float2bfloat16(a.y - __bfloat162float(h1));
        __nv_bfloat16 l2 = __float2bfloat16(a.z - __bfloat162float(h2));
        __nv_bfloat16 l3 = __float2bfloat16(a.w - __bfloat162float(h3));
        int o = m * APITCH + k4;
        *(__nv_bfloat162*)&as_hi[o]     = __nv_bfloat162(h0, h1);
        *(__nv_bfloat162*)&as_hi[o + 2] = __nv_bfloat162(h2, h3);
        *(__nv_bfloat162*)&as_lo[o]     = __nv_bfloat162(l0, l1);
        *(__nv_bfloat162*)&as_lo[o + 2] = __nv_bfloat162(l2, l3);
    }
    __syncthreads();

    float acc[2][4][4] = {};
    #pragma unroll 4
    for (int ks = 0; ks < 16; ++ks) {
        int kb = ks * 16;
        uint32_t ah[2][4], al[2][4], bh[4][2], bl[4][2];
        #pragma unroll
        for (int mf = 0; mf < 2; ++mf) {
            int r = wm * 32 + mf * 16 + g;
            int o0 = r * APITCH + kb + 2 * t;
            int o1 = (r + 8) * APITCH + kb + 2 * t;
            ah[mf][0] = *(const uint32_t*)&as_hi[o0];
            ah[mf][1] = *(const uint32_t*)&as_hi[o1];
            ah[mf][2] = *(const uint32_t*)&as_hi[o0 + 8];
            ah[mf][3] = *(const uint32_t*)&as_hi[o1 + 8];
            al[mf][0] = *(const uint32_t*)&as_lo[o0];
            al[mf][1] = *(const uint32_t*)&as_lo[o1];
            al[mf][2] = *(const uint32_t*)&as_lo[o0 + 8];
            al[mf][3] = *(const uint32_t*)&as_lo[o1 + 8];
        }
        #pragma unroll
        for (int nf = 0; nf < 4; ++nf) {
            int r = wn * 32 + nf * 8 + g;
            int o = r * BPITCH + kb + 2 * t;
            bh[nf][0] = *(const uint32_t*)&bs_hi[o];
            bh[nf][1] = *(const uint32_t*)&bs_hi[o + 8];
            bl[nf][0] = *(const uint32_t*)&bs_lo[o];
            bl[nf][1] = *(const uint32_t*)&bs_lo[o + 8];
        }
        #pragma unroll
        for (int mf = 0; mf < 2; ++mf)
            #pragma unroll
            for (int nf = 0; nf < 4; ++nf) {
                mma_bf16(acc[mf][nf], ah[mf], bh[nf]);
                mma_bf16(acc[mf][nf], ah[mf], bl[nf]);
                mma_bf16(acc[mf][nf], al[mf], bh[nf]);
            }
    }

    #pragma unroll
    for (int mf = 0; mf < 2; ++mf) {
        int r0 = m0 + wm * 32 + mf * 16 + g;
        #pragma unroll
        for (int nf = 0; nf < 4; ++nf) {
            int c = n0 + wn * 32 + nf * 8 + 2 * t;
            float bb0 = bias[c], bb1 = bias[c + 1];
            #pragma unroll
            for (int half = 0; half < 2; ++half) {
                int r = r0 + half * 8;
                float v0 = acc[mf][nf][half * 2 + 0] + bb0;
                float v1 = acc[mf][nf][half * 2 + 1] + bb1;
                if (HAS_ADD) {
                    v0 += add[(size_t)r * D + c];
                    v1 += add[(size_t)r * D + c + 1];
                }
                if (ACT == 1) {
                    float x0 = v0, x1 = v1;
                    float t0 = tanhf(0.7978845608028654f * (x0 + 0.044715f * x0 * x0 * x0));
                    float t1 = tanhf(0.7978845608028654f * (x1 + 0.044715f * x1 * x1 * x1));
                    v0 = 0.5f * x0 * (1.0f + t0);
                    v1 = 0.5f * x1 * (1.0f + t1);
                }
                float2 o2 = {v0, v1};
                *(float2*)&C[(size_t)r * D + c] = o2;
            }
        }
    }
}

template <int ACT, int AID, int CID, int ADDID>
__global__ void __launch_bounds__(256, 1) k_gemm_mma(int wslot, const float* __restrict__ bias) {
    gemm_mma_body<ACT, (ADDID >= 0)>(buf<AID>(), wslot, bias,
                                     (ADDID >= 0) ? buf<(ADDID >= 0 ? ADDID : 0)>() : nullptr,
                                     buf<CID>());
}

__global__ void __launch_bounds__(256, 1) k_gemm_mma_qkv(
        const float* __restrict__ bq, const float* __restrict__ bk,
        const float* __restrict__ bv) {
    const float* bias;
    float* C;
    if (blockIdx.z == 0)      { bias = bq; C = g_q; }
    else if (blockIdx.z == 1) { bias = bk; C = g_k; }
    else                      { bias = bv; C = g_v; }
    gemm_mma_body<0, false>(g_h, 1 + blockIdx.z, bias, nullptr, C);
}

// ---------------- 8: sparse masked attention ----------------
__global__ void k_attn() {
    __shared__ int s_cand[MAXC];
    __shared__ float s_sc[HN][MAXC];
    __shared__ int s_n;
    int e = blockIdx.x;
    int tid = threadIdx.x;
    int h = tid >> 5, lane = tid & 31;
    int a = g_src[e], b = g_dst[e];
    int oa = g_off[a];
    int na = g_off[a + 1] - oa;

    for (int i = tid; i < na; i += 128) s_cand[i] = g_inc[oa + i];

    if (tid < 32) {
        int cnt = na;
        if (b != a) {
            int ob = g_off[b];
            int nb = g_off[b + 1] - ob;
            for (int i0 = 0; i0 < nb; i0 += 32) {
                int i = i0 + lane;
                int f = 0, keep = 0;
                if (i < nb) {
                    f = g_inc[ob + i];
                    keep = (g_src[f] != a && g_dst[f] != a) ? 1 : 0;
                }
                unsigned bal = __ballot_sync(0xffffffffu, keep != 0);
                if (keep) {
                    int pos = cnt + __popc(bal & ((1u << lane) - 1u));
                    if (pos < MAXC) s_cand[pos] = f;
                }
                cnt += __popc(bal);
            }
        }
        if (lane == 0) s_n = (cnt < MAXC) ? cnt : MAXC;
    }
    __syncthreads();
    int nc = s_n;
    int base = e * D + h * DHD;

    float2 q2 = *(const float2*)&g_q[base + lane * 2];

    for (int c = 0; c < nc; ++c) {
        int f = s_cand[c];
        float2 k2 = *(const float2*)&g_k[f * D + h * DHD + lane * 2];
        float s = q2.x * k2.x + q2.y * k2.y;
        #pragma unroll
        for (int o = 16; o; o >>= 1) s += __shfl_xor_sync(0xffffffffu, s, o);
        if (lane == 0) s_sc[h][c] = s * 0.125f;
    }
    __syncwarp();

    float mx = -3.0e38f;
    for (int c = lane; c < nc; c += 32) mx = fmaxf(mx, s_sc[h][c]);
    #pragma unroll
    for (int o = 16; o; o >>= 1) mx = fmaxf(mx, __shfl_xor_sync(0xffffffffu, mx, o));
    float l = 0.f;
    for (int c = lane; c < nc; c += 32) {
        float p = __expf(s_sc[h][c] - mx);
        s_sc[h][c] = p;
        l += p;
    }
    #pragma unroll
    for (int o = 16; o; o >>= 1) l += __shfl_xor_sync(0xffffffffu, l, o);
    __syncwarp();

    float ax = 0.f, ay = 0.f;
    for (int c = 0; c < nc; ++c) {
        float p = s_sc[h][c];
        float2 v2 = *(const float2*)&g_v[s_cand[c] * D + h * DHD + lane * 2];
        ax += p * v2.x;
        ay += p * v2.y;
    }
    float inv = 1.f / l;
    float2 r;
    r.x = ax * inv;
    r.y = ay * inv;
    *(float2*)&g_ao[base + lane * 2] = r;
}

// ---------------- 9: classifier ----------------
__global__ void k_cls(const float* __restrict__ W2, const float* __restrict__ b2,
                      float* __restrict__ out) {
    int warp = (blockIdx.x * blockDim.x + threadIdx.x) >> 5;
    int lane = threadIdx.x & 31;
    if (warp >= NE) return;
    float x[8];
    #pragma unroll
    for (int i = 0; i < 8; ++i) x[i] = g_hid[(size_t)warp * D + lane + i * 32];
    float res = 0.f;
    #pragma unroll
    for (int c = 0; c < CLS; ++c) {
        float s = 0.f;
        #pragma unroll
        for (int i = 0; i < 8; ++i) s += x[i] * W2[(size_t)(lane + i * 32) * CLS + c];
        #pragma unroll
        for (int o = 16; o; o >>= 1) s += __shfl_xor_sync(0xffffffffu, s, o);
        if (lane == c) res = s + b2[c];
    }
    if (lane < CLS) out[(size_t)warp * CLS + lane] = res;
}

// ---------------- host ----------------
extern "C" void kernel_launch(void* const* d_in, const int* in_sizes, int n_in,
                              void* d_out, int out_size) {
    const float* nf   = (const float*)d_in[0];
    const float* efi  = (const float*)d_in[1];
    const int*   ei   = (const int*)d_in[2];
    const float* Wn_r = (const float*)d_in[3];
    const float* bn_r = (const float*)d_in[4];
    const float* We_r = (const float*)d_in[5];
    const float* be_r = (const float*)d_in[6];
    const float* Wnp  = (const float*)d_in[7];
    const float* bnp  = (const float*)d_in[8];
    const float* Wq   = (const float*)d_in[9];
    const float* bq   = (const float*)d_in[10];
    const float* Wk   = (const float*)d_in[11];
    const float* bk   = (const float*)d_in[12];
    const float* Wv   = (const float*)d_in[13];
    const float* bv   = (const float*)d_in[14];
    const float* Wo   = (const float*)d_in[15];
    const float* bo   = (const float*)d_in[16];
    const float* W1   = (const float*)d_in[17];
    const float* b1   = (const float*)d_in[18];
    const float* W2   = (const float*)d_in[19];
    const float* b2   = (const float*)d_in[20];
    float* out = (float*)d_out;

    cudaFuncSetAttribute(k_gemm_mma<0, 0, 2, 1>, cudaFuncAttributeMaxDynamicSharedMemorySize, MMA_SMEM_BYTES);
    cudaFuncSetAttribute(k_gemm_mma_qkv, cudaFuncAttributeMaxDynamicSharedMemorySize, MMA_SMEM_BYTES);
    cudaFuncSetAttribute(k_gemm_mma<0, 6, 7, -1>, cudaFuncAttributeMaxDynamicSharedMemorySize, MMA_SMEM_BYTES);
    cudaFuncSetAttribute(k_gemm_mma<1, 7, 8, -1>, cudaFuncAttributeMaxDynamicSharedMemorySize, MMA_SMEM_BYTES);

    k_prepw<<<dim3(4, 4, 6), 256>>>(Wnp, Wq, Wk, Wv, Wo, W1);
    k_convert<<<16, 256>>>(ei);
    k_scores<<<((NN + NE) * 32 + 255) / 256, 256>>>(nf, efi, Wn_r, bn_r, We_r, be_r);
    k_topk<<<2, 1024>>>();
    k_scan<<<1, 1024>>>();
    k_fill_at<<<(NE + 255) / 256, 256>>>();
    k_sortinc<<<(NN + 255) / 256, 256>>>();
    k_prepare<<<NE, 256>>>(nf, efi);

    dim3 gg(D / 64, NE / 128);      // (4, 32)
    dim3 gq(D / 64, NE / 128, 3);   // fused q/k/v
    k_gemm_mma<0, 0, 2, 1><<<gg, 256, MMA_SMEM_BYTES>>>(0, bnp);     // h = gs@Wnp + bnp + ef
    k_gemm_mma_qkv<<<gq, 256, MMA_SMEM_BYTES>>>(bq, bk, bv);         // q,k,v
    k_attn<<<NE, 128>>>();
    k_gemm_mma<0, 6, 7, -1><<<gg, 256, MMA_SMEM_BYTES>>>(4, bo);     // o = ao@Wo + bo
    k_gemm_mma<1, 7, 8, -1><<<gg, 256, MMA_SMEM_BYTES>>>(5, b1);     // hid = gelu(o@W1 + b1)
    k_cls<<<(NE * 32 + 255) / 256, 256>>>(W2, b2, out);
}

// round 8
// speedup vs baseline: 3.7564x; 1.2424x over previous
#include <cuda_runtime.h>
#include <cuda_bf16.h>
#include <math.h>
#include <stdint.h>

#define NN    1024
#define NE    4096
#define D     256
#define HN    4
#define DHD   64
#define NODEK 512
#define EDGEK 2048
#define CLS   16
#define MAXC  1024

// mma.sync GEMM tile: CTA 128x64, K=256 resident, 8 warps (4m x 2n), warp 32x32
#define APITCH 264
#define BPITCH 264
#define OFF_AHI 0
#define OFF_ALO (128 * APITCH)
#define OFF_BHI (2 * 128 * APITCH)
#define OFF_BLO (2 * 128 * APITCH + 64 * BPITCH)
#define MMA_SMEM_ELEMS (2 * 128 * APITCH + 2 * 64 * BPITCH)
#define MMA_SMEM_BYTES (MMA_SMEM_ELEMS * 2)

// ---------------- scratch ----------------
__device__ float g_nscore[NN];
__device__ float g_escore[NE];
__device__ int   g_nmask[NN];
__device__ int   g_emask[NE];
__device__ int   g_src[NE], g_dst[NE];
__device__ int   g_off[NN + 1];
__device__ int   g_inc[2 * NE];
__device__ float g_h[NE * D];    // 2
__device__ float g_q[NE * D];    // 3
__device__ float g_k[NE * D];    // 4
__device__ float g_v[NE * D];    // 5
__device__ float g_ao[NE * D];   // 6
__device__ float g_o[NE * D];    // 7
__device__ float g_hid[NE * D];  // 8
// transposed split-bf16 weights: [w][n][k], w: 0=Wnp 1=Wq 2=Wk 3=Wv 4=Wo 5=W1
__device__ __nv_bfloat16 g_wthi[6 * D * D];
__device__ __nv_bfloat16 g_wtlo[6 * D * D];

template <int ID> __device__ __forceinline__ float* buf();
template <> __device__ __forceinline__ float* buf<2>() { return g_h; }
template <> __device__ __forceinline__ float* buf<3>() { return g_q; }
template <> __device__ __forceinline__ float* buf<4>() { return g_k; }
template <> __device__ __forceinline__ float* buf<5>() { return g_v; }
template <> __device__ __forceinline__ float* buf<6>() { return g_ao; }
template <> __device__ __forceinline__ float* buf<7>() { return g_o; }
template <> __device__ __forceinline__ float* buf<8>() { return g_hid; }

// ================= 1: fused front-end =================
// blocks [0,96)  : weight prep (split-bf16 + transpose), 6 weights x 16 tiles
// blocks [96,112): edge_index convert (self-detecting dtype)
// blocks [112,752): router scores, warp per row (5120 rows exactly)
__global__ void k_front(const float* __restrict__ nf, const float* __restrict__ efi,
                        const int* __restrict__ ei,
                        const float* __restrict__ Wn, const float* __restrict__ bn,
                        const float* __restrict__ We, const float* __restrict__ be,
                        const float* __restrict__ Wnp, const float* __restrict__ Wq,
                        const float* __restrict__ Wk, const float* __restrict__ Wv,
                        const float* __restrict__ Wo, const float* __restrict__ W1) {
    int b = blockIdx.x;
    int tid = threadIdx.x;
    if (b < 96) {
        // ---- weight prep ----
        __shared__ float s[64][65];
        int w = b >> 4, t16 = b & 15;
        const float* W;
        switch (w) {
            case 0: W = Wnp; break;
            case 1: W = Wq; break;
            case 2: W = Wk; break;
            case 3: W = Wv; break;
            case 4: W = Wo; break;
            default: W = W1; break;
        }
        int n0 = (t16 & 3) * 64, k0 = (t16 >> 2) * 64;
        int n4 = (tid & 15) * 4, kr = tid >> 4;
        #pragma unroll
        for (int kk = kr; kk < 64; kk += 16) {
            float4 v = *(const float4*)&W[(size_t)(k0 + kk) * D + n0 + n4];
            s[kk][n4] = v.x;
            s[kk][n4 + 1] = v.y;
            s[kk][n4 + 2] = v.z;
            s[kk][n4 + 3] = v.w;
        }
        __syncthreads();
        int nl = tid >> 2, kq = (tid & 3) * 16;
        __nv_bfloat16 hi[16], lo[16];
        #pragma unroll
        for (int i = 0; i < 16; ++i) {
            float x = s[kq + i][nl];
            hi[i] = __float2bfloat16(x);
            lo[i] = __float2bfloat16(x - __bfloat162float(hi[i]));
        }
        size_t off = (size_t)w * D * D + (size_t)(n0 + nl) * D + k0 + kq;
        *(uint4*)&g_wthi[off] = *(uint4*)&hi[0];
        *(uint4*)&g_wthi[off + 8] = *(uint4*)&hi[8];
        *(uint4*)&g_wtlo[off] = *(uint4*)&lo[0];
        *(uint4*)&g_wtlo[off + 8] = *(uint4*)&lo[8];
    } else if (b < 112) {
        // ---- edge_index convert (dtype detect per block; redundant but cheap) ----
        __shared__ int sh[256];
        int acc = 0;
        for (int i = tid; i < 2048; i += 256) acc |= ei[2 * i + 1];
        sh[tid] = acc;
        __syncthreads();
        for (int s2 = 128; s2 > 0; s2 >>= 1) {
            if (tid < s2) sh[tid] |= sh[tid + s2];
            __syncthreads();
        }
        int is64 = (sh[0] == 0) ? 1 : 0;
        int i = (b - 96) * 256 + tid;
        int s, d;
        if (is64) { s = ei[2 * i]; d = ei[2 * (NE + i)]; }
        else      { s = ei[i];     d = ei[NE + i]; }
        g_src[i] = s;
        g_dst[i] = d;
    } else {
        // ---- router scores ----
        int warp = (b - 112) * 8 + (tid >> 5);
        int lane = tid & 31;
        const float* x;
        const float* w;
        if (warp < NN) { x = nf + (size_t)warp * D; w = Wn; }
        else           { x = efi + (size_t)(warp - NN) * D; w = We; }
        float s = 0.f;
        #pragma unroll
        for (int i = 0; i < D / 32; ++i) s += x[lane + i * 32] * w[lane + i * 32];
        #pragma unroll
        for (int o = 16; o; o >>= 1) s += __shfl_xor_sync(0xffffffffu, s, o);
        if (lane == 0) {
            if (warp < NN) g_nscore[warp] = s + bn[0];
            else           g_escore[warp - NN] = s + be[0];
        }
    }
}

// ================= 2: fused build =================
// block 0: node top-k, block 1: edge top-k (radix select, exact w/ ties)
// block 2: full incidence build (count + scan + fill + sort) in smem
struct TkSmem {
    unsigned su[NE];
    int hist[256];
    unsigned pref;
    int krem;
    int wagg[32];
};
struct IncSmem {
    int cnt[NN];
    int off[NN];
    int pos[NN];
    int inc[2 * NE];
};
union BuildSmem {
    TkSmem tk;
    IncSmem in;
};

__global__ void __launch_bounds__(1024, 1) k_build() {
    __shared__ BuildSmem sm;
    int tid = threadIdx.x;
    int lane = tid & 31, wid = tid >> 5;

    if (blockIdx.x < 2) {
        const bool is_edge = (blockIdx.x == 1);
        const float* sc = is_edge ? g_escore : g_nscore;
        int* mask = is_edge ? g_emask : g_nmask;
        const int n = is_edge ? NE : NN;
        const int kk = is_edge ? EDGEK : NODEK;
        int items = n >> 10;

        for (int j = 0; j < items; ++j) {
            int i = tid * items + j;
            unsigned bb = __float_as_uint(sc[i]);
            sm.tk.su[i] = (bb & 0x80000000u) ? ~bb : (bb | 0x80000000u);
        }
        if (tid == 0) { sm.tk.pref = 0u; sm.tk.krem = kk; }
        __syncthreads();

        for (int shift = 24; shift >= 0; shift -= 8) {
            unsigned prefix = sm.tk.pref;
            unsigned done_mask = (shift == 24) ? 0u : (0xFFFFFFFFu << (shift + 8));
            if (tid < 256) sm.tk.hist[tid] = 0;
            __syncthreads();
            for (int j = 0; j < items; ++j) {
                unsigned u = sm.tk.su[tid * items + j];
                if ((u & done_mask) == prefix)
                    atomicAdd(&sm.tk.hist[(u >> shift) & 255], 1);
            }
            __syncthreads();
            if (wid == 0) {
                int krem = sm.tk.krem;
                int gsum = 0;
                #pragma unroll
                for (int c = 0; c < 8; ++c) gsum += sm.tk.hist[lane * 8 + c];
                int x = gsum;
                #pragma unroll
                for (int off = 1; off < 32; off <<= 1) {
                    int t = __shfl_down_sync(0xffffffffu, x, off);
                    if (lane + off < 32) x += t;
                }
                int above = x - gsum;
                bool hit = (above < krem) && (x >= krem);
                unsigned bal = __ballot_sync(0xffffffffu, hit);
                int srcl = __ffs(bal) - 1;
                if (lane == srcl) {
                    int cum = above;
                    #pragma unroll
                    for (int c = 7; c >= 0; --c) {
                        int bb = lane * 8 + c;
                        int hc = sm.tk.hist[bb];
                        if (cum + hc >= krem) {
                            sm.tk.pref = prefix | ((unsigned)bb << shift);
                            sm.tk.krem = krem - cum;
                            break;
                        }
                        cum += hc;
                    }
                }
            }
            __syncthreads();
        }
        unsigned T = sm.tk.pref;
        int r = sm.tk.krem;

        int ct = 0;
        for (int j = 0; j < items; ++j) ct += (sm.tk.su[tid * items + j] == T) ? 1 : 0;
        int scan = ct;
        #pragma unroll
        for (int off = 1; off < 32; off <<= 1) {
            int t = __shfl_up_sync(0xffffffffu, scan, off);
            if (lane >= off) scan += t;
        }
        if (lane == 31) sm.tk.wagg[wid] = scan;
        __syncthreads();
        if (wid == 0) {
            int v = sm.tk.wagg[lane];
            #pragma unroll
            for (int off = 1; off < 32; off <<= 1) {
                int t = __shfl_up_sync(0xffffffffu, v, off);
                if (lane >= off) v += t;
            }
            sm.tk.wagg[lane] = v;
        }
        __syncthreads();
        int excl = (wid > 0 ? sm.tk.wagg[wid - 1] : 0) + scan - ct;

        for (int j = 0; j < items; ++j) {
            int i = tid * items + j;
            unsigned u = sm.tk.su[i];
            int mk;
            if (u > T) mk = 1;
            else if (u == T) { mk = (excl < r) ? 1 : 0; excl++; }
            else mk = 0;
            mask[i] = mk;
        }
    } else {
        // ---- incidence build ----
        sm.in.cnt[tid] = 0;
        __syncthreads();
        #pragma unroll
        for (int j = 0; j < 4; ++j) {
            int e = j * 1024 + tid;
            int a = g_src[e], b = g_dst[e];
            atomicAdd(&sm.in.cnt[a], 1);
            if (b != a) atomicAdd(&sm.in.cnt[b], 1);
        }
        __syncthreads();
        // Hillis-Steele inclusive scan on cnt
        int own = sm.in.cnt[tid];
        int val = own;
        for (int dd = 1; dd < 1024; dd <<= 1) {
            int t = (tid >= dd) ? sm.in.cnt[tid - dd] : 0;
            __syncthreads();
            val += t;
            sm.in.cnt[tid] = val;
            __syncthreads();
        }
        int offv = val - own;
        sm.in.off[tid] = offv;
        sm.in.pos[tid] = offv;
        if (tid == 1023) g_off[1024] = val;
        g_off[tid] = offv;
        __syncthreads();
        int total = sm.in.off[1023] + (sm.in.cnt[1023] - sm.in.off[1023]);  // = last inclusive
        // atomic fill
        #pragma unroll
        for (int j = 0; j < 4; ++j) {
            int e = j * 1024 + tid;
            int a = g_src[e], b = g_dst[e];
            sm.in.inc[atomicAdd(&sm.in.pos[a], 1)] = e;
            if (b != a) sm.in.inc[atomicAdd(&sm.in.pos[b], 1)] = e;
        }
        __syncthreads();
        // per-node insertion sort (deterministic index order)
        {
            int s = sm.in.off[tid];
            int t = sm.in.pos[tid];
            for (int i = s + 1; i < t; ++i) {
                int v = sm.in.inc[i];
                int j = i - 1;
                while (j >= s && sm.in.inc[j] > v) { sm.in.inc[j + 1] = sm.in.inc[j]; --j; }
                sm.in.inc[j + 1] = v;
            }
        }
        __syncthreads();
        for (int i = tid; i < total; i += 1024) g_inc[i] = sm.in.inc[i];
    }
}

// ================= GEMM (split-bf16 mma.sync) =================
__device__ __forceinline__ void mma_bf16(float* c, const uint32_t* a, const uint32_t* b) {
    asm volatile(
        "mma.sync.aligned.m16n8k16.row.col.f32.bf16.bf16.f32 "
        "{%0,%1,%2,%3}, {%4,%5,%6,%7}, {%8,%9}, {%0,%1,%2,%3};"
        : "+f"(c[0]), "+f"(c[1]), "+f"(c[2]), "+f"(c[3])
        : "r"(a[0]), "r"(a[1]), "r"(a[2]), "r"(a[3]), "r"(b[0]), "r"(b[1]));
}

__device__ __forceinline__ void fill_b(__nv_bfloat16* bs_hi, __nv_bfloat16* bs_lo,
                                       int wslot, int n0, int tid) {
    const __nv_bfloat16* Bh = g_wthi + (size_t)wslot * D * D;
    const __nv_bfloat16* Bl = g_wtlo + (size_t)wslot * D * D;
    #pragma unroll
    for (int it = 0; it < 8; ++it) {
        int idx = it * 256 + tid;
        int n = idx >> 5, kq = (idx & 31) * 8;
        uint4 vh = *(const uint4*)&Bh[(size_t)(n0 + n) * D + kq];
        uint4 vl = *(const uint4*)&Bl[(size_t)(n0 + n) * D + kq];
        *(uint4*)&bs_hi[n * BPITCH + kq] = vh;
        *(uint4*)&bs_lo[n * BPITCH + kq] = vl;
    }
}

__device__ __forceinline__ void split_store_a(__nv_bfloat16* as_hi, __nv_bfloat16* as_lo,
                                              int o, float4 a) {
    __nv_bfloat16 h0 = __float2bfloat16(a.x), h1 = __float2bfloat16(a.y);
    __nv_bfloat16 h2 = __float2bfloat16(a.z), h3 = __float2bfloat16(a.w);
    __nv_bfloat16 l0 = __float2bfloat16(a.x - __bfloat162float(h0));
    __nv_bfloat16 l1 = __float2bfloat16(a.y - __bfloat162float(h1));
    __nv_bfloat16 l2 = __float2bfloat16(a.z - __bfloat162float(h2));
    __nv_bfloat16 l3 = __float2bfloat16(a.w - __bfloat162float(h3));
    *(__nv_bfloat162*)&as_hi[o]     = __nv_bfloat162(h0, h1);
    *(__nv_bfloat162*)&as_hi[o + 2] = __nv_bfloat162(h2, h3);
    *(__nv_bfloat162*)&as_lo[o]     = __nv_bfloat162(l0, l1);
    *(__nv_bfloat162*)&as_lo[o + 2] = __nv_bfloat162(l2, l3);
}

// core mma loop + epilogue helper (acc produced in-place)
__device__ __forceinline__ void mma_loop(const __nv_bfloat16* as_hi, const __nv_bfloat16* as_lo,
                                         const __nv_bfloat16* bs_hi, const __nv_bfloat16* bs_lo,
                                         int wm, int wn, int g, int t, float acc[2][4][4]) {
    #pragma unroll 4
    for (int ks = 0; ks < 16; ++ks) {
        int kb = ks * 16;
        uint32_t ah[2][4], al[2][4], bh[4][2], bl[4][2];
        #pragma unroll
        for (int mf = 0; mf < 2; ++mf) {
            int r = wm * 32 + mf * 16 + g;
            int o0 = r * APITCH + kb + 2 * t;
            int o1 = (r + 8) * APITCH + kb + 2 * t;
            ah[mf][0] = *(const uint32_t*)&as_hi[o0];
            ah[mf][1] = *(const uint32_t*)&as_hi[o1];
            ah[mf][2] = *(const uint32_t*)&as_hi[o0 + 8];
            ah[mf][3] = *(const uint32_t*)&as_hi[o1 + 8];
            al[mf][0] = *(const uint32_t*)&as_lo[o0];
            al[mf][1] = *(const uint32_t*)&as_lo[o1];
            al[mf][2] = *(const uint32_t*)&as_lo[o0 + 8];
            al[mf][3] = *(const uint32_t*)&as_lo[o1 + 8];
        }
        #pragma unroll
        for (int nf = 0; nf < 4; ++nf) {
            int r = wn * 32 + nf * 8 + g;
            int o = r * BPITCH + kb + 2 * t;
            bh[nf][0] = *(const uint32_t*)&bs_hi[o];
            bh[nf][1] = *(const uint32_t*)&bs_hi[o + 8];
            bl[nf][0] = *(const uint32_t*)&bs_lo[o];
            bl[nf][1] = *(const uint32_t*)&bs_lo[o + 8];
        }
        #pragma unroll
        for (int mf = 0; mf < 2; ++mf)
            #pragma unroll
            for (int nf = 0; nf < 4; ++nf) {
                mma_bf16(acc[mf][nf], ah[mf], bh[nf]);
                mma_bf16(acc[mf][nf], ah[mf], bl[nf]);
                mma_bf16(acc[mf][nf], al[mf], bh[nf]);
            }
    }
}

template <int ACT, bool HAS_ADD>
__device__ __forceinline__ void gemm_mma_body(const float* __restrict__ A, int wslot,
                                              const float* __restrict__ bias,
                                              const float* __restrict__ add,
                                              float* __restrict__ C) {
    extern __shared__ __nv_bfloat16 smx[];
    __nv_bfloat16* as_hi = smx + OFF_AHI;
    __nv_bfloat16* as_lo = smx + OFF_ALO;
    __nv_bfloat16* bs_hi = smx + OFF_BHI;
    __nv_bfloat16* bs_lo = smx + OFF_BLO;

    int tid = threadIdx.x;
    int wid = tid >> 5, lane = tid & 31;
    int g = lane >> 2, t = lane & 3;
    int wm = wid >> 1, wn = wid & 1;
    int m0 = blockIdx.y * 128, n0 = blockIdx.x * 64;

    fill_b(bs_hi, bs_lo, wslot, n0, tid);
    #pragma unroll
    for (int it = 0; it < 32; ++it) {
        int idx = it * 256 + tid;
        int m = idx >> 6, k4 = (idx & 63) * 4;
        float4 a = *(const float4*)&A[(size_t)(m0 + m) * D + k4];
        split_store_a(as_hi, as_lo, m * APITCH + k4, a);
    }
    __syncthreads();

    float acc[2][4][4] = {};
    mma_loop(as_hi, as_lo, bs_hi, bs_lo, wm, wn, g, t, acc);

    #pragma unroll
    for (int mf = 0; mf < 2; ++mf) {
        int r0 = m0 + wm * 32 + mf * 16 + g;
        #pragma unroll
        for (int nf = 0; nf < 4; ++nf) {
            int c = n0 + wn * 32 + nf * 8 + 2 * t;
            float bb0 = bias[c], bb1 = bias[c + 1];
            #pragma unroll
            for (int half = 0; half < 2; ++half) {
                int r = r0 + half * 8;
                float v0 = acc[mf][nf][half * 2 + 0] + bb0;
                float v1 = acc[mf][nf][half * 2 + 1] + bb1;
                if (HAS_ADD) {
                    v0 += add[(size_t)r * D + c];
                    v1 += add[(size_t)r * D + c + 1];
                }
                if (ACT == 1) {
                    float x0 = v0, x1 = v1;
                    float t0 = tanhf(0.7978845608028654f * (x0 + 0.044715f * x0 * x0 * x0));
                    float t1 = tanhf(0.7978845608028654f * (x1 + 0.044715f * x1 * x1 * x1));
                    v0 = 0.5f * x0 * (1.0f + t0);
                    v1 = 0.5f * x1 * (1.0f + t1);
                }
                float2 o2 = {v0, v1};
                *(float2*)&C[(size_t)r * D + c] = o2;
            }
        }
    }
}

// gemm h: A generated on the fly (nf[src]+nf[dst]); epilogue adds masked ef
__global__ void __launch_bounds__(256, 1) k_gemm_h(const float* __restrict__ nf,
                                                   const float* __restrict__ efi,
                                                   const float* __restrict__ bias) {
    extern __shared__ __nv_bfloat16 smx[];
    __nv_bfloat16* as_hi = smx + OFF_AHI;
    __nv_bfloat16* as_lo = smx + OFF_ALO;
    __nv_bfloat16* bs_hi = smx + OFF_BHI;
    __nv_bfloat16* bs_lo = smx + OFF_BLO;

    int tid = threadIdx.x;
    int wid = tid >> 5, lane = tid & 31;
    int g = lane >> 2, t = lane & 3;
    int wm = wid >> 1, wn = wid & 1;
    int m0 = blockIdx.y * 128, n0 = blockIdx.x * 64;

    fill_b(bs_hi, bs_lo, 0, n0, tid);
    #pragma unroll
    for (int it = 0; it < 32; ++it) {
        int idx = it * 256 + tid;
        int m = idx >> 6, k4 = (idx & 63) * 4;
        int e = m0 + m;
        int a = g_src[e], b = g_dst[e];
        float4 xa = *(const float4*)&nf[(size_t)a * D + k4];
        float4 xb = *(const float4*)&nf[(size_t)b * D + k4];
        float4 s = {xa.x + xb.x, xa.y + xb.y, xa.z + xb.z, xa.w + xb.w};
        split_store_a(as_hi, as_lo, m * APITCH + k4, s);
    }
    __syncthreads();

    float acc[2][4][4] = {};
    mma_loop(as_hi, as_lo, bs_hi, bs_lo, wm, wn, g, t, acc);

    #pragma unroll
    for (int mf = 0; mf < 2; ++mf) {
        int r0 = m0 + wm * 32 + mf * 16 + g;
        #pragma unroll
        for (int half = 0; half < 2; ++half) {
            int r = r0 + half * 8;
            int em = g_emask[r] & g_nmask[g_src[r]] & g_nmask[g_dst[r]];
            float fm = em ? 1.0f : 0.0f;
            #pragma unroll
            for (int nf = 0; nf < 4; ++nf) {
                int c = n0 + wn * 32 + nf * 8 + 2 * t;
                float v0 = acc[mf][nf][half * 2 + 0] + bias[c]
                         + fm * efi[(size_t)r * D + c];
                float v1 = acc[mf][nf][half * 2 + 1] + bias[c + 1]
                         + fm * efi[(size_t)r * D + c + 1];
                float2 o2 = {v0, v1};
                *(float2*)&g_h[(size_t)r * D + c] = o2;
            }
        }
    }
}

template <int ACT, int AID, int CID>
__global__ void __launch_bounds__(256, 1) k_gemm_mma(int wslot, const float* __restrict__ bias) {
    gemm_mma_body<ACT, false>(buf<AID>(), wslot, bias, nullptr, buf<CID>());
}

__global__ void __launch_bounds__(256, 1) k_gemm_mma_qkv(
        const float* __restrict__ bq, const float* __restrict__ bk,
        const float* __restrict__ bv) {
    const float* bias;
    float* C;
    if (blockIdx.z == 0)      { bias = bq; C = g_q; }
    else if (blockIdx.z == 1) { bias = bk; C = g_k; }
    else                      { bias = bv; C = g_v; }
    gemm_mma_body<0, false>(g_h, 1 + blockIdx.z, bias, nullptr, C);
}

// ================= sparse masked attention =================
__global__ void k_attn() {
    __shared__ int s_cand[MAXC];
    __shared__ float s_sc[HN][MAXC];
    __shared__ int s_n;
    int e = blockIdx.x;
    int tid = threadIdx.x;
    int h = tid >> 5, lane = tid & 31;
    int a = g_src[e], b = g_dst[e];
    int oa = g_off[a];
    int na = g_off[a + 1] - oa;

    for (int i = tid; i < na; i += 128) s_cand[i] = g_inc[oa + i];

    if (tid < 32) {
        int cnt = na;
        if (b != a) {
            int ob = g_off[b];
            int nb = g_off[b + 1] - ob;
            for (int i0 = 0; i0 < nb; i0 += 32) {
                int i = i0 + lane;
                int f = 0, keep = 0;
                if (i < nb) {
                    f = g_inc[ob + i];
                    keep = (g_src[f] != a && g_dst[f] != a) ? 1 : 0;
                }
                unsigned bal = __ballot_sync(0xffffffffu, keep != 0);
                if (keep) {
                    int pos = cnt + __popc(bal & ((1u << lane) - 1u));
                    if (pos < MAXC) s_cand[pos] = f;
                }
                cnt += __popc(bal);
            }
        }
        if (lane == 0) s_n = (cnt < MAXC) ? cnt : MAXC;
    }
    __syncthreads();
    int nc = s_n;
    int base = e * D + h * DHD;

    float2 q2 = *(const float2*)&g_q[base + lane * 2];

    for (int c = 0; c < nc; ++c) {
        int f = s_cand[c];
        float2 k2 = *(const float2*)&g_k[f * D + h * DHD + lane * 2];
        float s = q2.x * k2.x + q2.y * k2.y;
        #pragma unroll
        for (int o = 16; o; o >>= 1) s += __shfl_xor_sync(0xffffffffu, s, o);
        if (lane == 0) s_sc[h][c] = s * 0.125f;
    }
    __syncwarp();

    float mx = -3.0e38f;
    for (int c = lane; c < nc; c += 32) mx = fmaxf(mx, s_sc[h][c]);
    #pragma unroll
    for (int o = 16; o; o >>= 1) mx = fmaxf(mx, __shfl_xor_sync(0xffffffffu, mx, o));
    float l = 0.f;
    for (int c = lane; c < nc; c += 32) {
        float p = __expf(s_sc[h][c] - mx);
        s_sc[h][c] = p;
        l += p;
    }
    #pragma unroll
    for (int o = 16; o; o >>= 1) l += __shfl_xor_sync(0xffffffffu, l, o);
    __syncwarp();

    float ax = 0.f, ay = 0.f;
    for (int c = 0; c < nc; ++c) {
        float p = s_sc[h][c];
        float2 v2 = *(const float2*)&g_v[s_cand[c] * D + h * DHD + lane * 2];
        ax += p * v2.x;
        ay += p * v2.y;
    }
    float inv = 1.f / l;
    float2 r;
    r.x = ax * inv;
    r.y = ay * inv;
    *(float2*)&g_ao[base + lane * 2] = r;
}

// ================= classifier =================
__global__ void k_cls(const float* __restrict__ W2, const float* __restrict__ b2,
                      float* __restrict__ out) {
    int warp = (blockIdx.x * blockDim.x + threadIdx.x) >> 5;
    int lane = threadIdx.x & 31;
    if (warp >= NE) return;
    float x[8];
    #pragma unroll
    for (int i = 0; i < 8; ++i) x[i] = g_hid[(size_t)warp * D + lane + i * 32];
    float res = 0.f;
    #pragma unroll
    for (int c = 0; c < CLS; ++c) {
        float s = 0.f;
        #pragma unroll
        for (int i = 0; i < 8; ++i) s += x[i] * W2[(size_t)(lane + i * 32) * CLS + c];
        #pragma unroll
        for (int o = 16; o; o >>= 1) s += __shfl_xor_sync(0xffffffffu, s, o);
        if (lane == c) res = s + b2[c];
    }
    if (lane < CLS) out[(size_t)warp * CLS + lane] = res;
}

// ================= host =================
extern "C" void kernel_launch(void* const* d_in, const int* in_sizes, int n_in,
                              void* d_out, int out_size) {
    const float* nf   = (const float*)d_in[0];
    const float* efi  = (const float*)d_in[1];
    const int*   ei   = (const int*)d_in[2];
    const float* Wn_r = (const float*)d_in[3];
    const float* bn_r = (const float*)d_in[4];
    const float* We_r = (const float*)d_in[5];
    const float* be_r = (const float*)d_in[6];
    const float* Wnp  = (const float*)d_in[7];
    const float* bnp  = (const float*)d_in[8];
    const float* Wq   = (const float*)d_in[9];
    const float* bq   = (const float*)d_in[10];
    const float* Wk   = (const float*)d_in[11];
    const float* bk   = (const float*)d_in[12];
    const float* Wv   = (const float*)d_in[13];
    const float* bv   = (const float*)d_in[14];
    const float* Wo   = (const float*)d_in[15];
    const float* bo   = (const float*)d_in[16];
    const float* W1   = (const float*)d_in[17];
    const float* b1   = (const float*)d_in[18];
    const float* W2   = (const float*)d_in[19];
    const float* b2   = (const float*)d_in[20];
    float* out = (float*)d_out;

    cudaFuncSetAttribute(k_gemm_h, cudaFuncAttributeMaxDynamicSharedMemorySize, MMA_SMEM_BYTES);
    cudaFuncSetAttribute(k_gemm_mma_qkv, cudaFuncAttributeMaxDynamicSharedMemorySize, MMA_SMEM_BYTES);
    cudaFuncSetAttribute(k_gemm_mma<0, 6, 7>, cudaFuncAttributeMaxDynamicSharedMemorySize, MMA_SMEM_BYTES);
    cudaFuncSetAttribute(k_gemm_mma<1, 7, 8>, cudaFuncAttributeMaxDynamicSharedMemorySize, MMA_SMEM_BYTES);

    k_front<<<752, 256>>>(nf, efi, ei, Wn_r, bn_r, We_r, be_r, Wnp, Wq, Wk, Wv, Wo, W1);
    k_build<<<3, 1024>>>();

    dim3 gg(D / 64, NE / 128);      // (4, 32)
    dim3 gq(D / 64, NE / 128, 3);   // fused q/k/v
    k_gemm_h<<<gg, 256, MMA_SMEM_BYTES>>>(nf, efi, bnp);            // h = (nf[s]+nf[d])@Wnp + bnp + mask*ef
    k_gemm_mma_qkv<<<gq, 256, MMA_SMEM_BYTES>>>(bq, bk, bv);        // q,k,v
    k_attn<<<NE, 128>>>();
    k_gemm_mma<0, 6, 7><<<gg, 256, MMA_SMEM_BYTES>>>(4, bo);        // o = ao@Wo + bo
    k_gemm_mma<1, 7, 8><<<gg, 256, MMA_SMEM_BYTES>>>(5, b1);        // hid = gelu(o@W1 + b1)
    k_cls<<<(NE * 32 + 255) / 256, 256>>>(W2, b2, out);
}

// round 9
// speedup vs baseline: 3.8140x; 1.0153x over previous
#include <cuda_runtime.h>
#include <cuda_bf16.h>
#include <math.h>
#include <stdint.h>

#define NN    1024
#define NE    4096
#define D     256
#define HN    4
#define DHD   64
#define NODEK 512
#define EDGEK 2048
#define CLS   16
#define MAXC  1024

// mma.sync GEMM: CTA 128x64, K chunked (2 x 128), 8 warps (4m x 2n), warp 32x32
// smem 102KB -> 2 CTAs/SM, launch_bounds caps regs at 128 (no spills)
#define KC     128
#define APITCH 136
#define BPITCH 136
#define OFF_AHI 0
#define OFF_ALO (128 * APITCH)
#define OFF_BHI (2 * 128 * APITCH)
#define OFF_BLO (2 * 128 * APITCH + 64 * BPITCH)
#define MMA_SMEM_ELEMS (2 * 128 * APITCH + 2 * 64 * BPITCH)
#define MMA_SMEM_BYTES (MMA_SMEM_ELEMS * 2)   // 104448 B

// ---------------- scratch ----------------
__device__ float g_nscore[NN];
__device__ float g_escore[NE];
__device__ int   g_nmask[NN];
__device__ int   g_emask[NE];
__device__ int   g_src[NE], g_dst[NE];
__device__ int   g_off[NN + 1];
__device__ int   g_inc[2 * NE];
__device__ float g_h[NE * D];    // 2
__device__ float g_q[NE * D];    // 3
__device__ float g_k[NE * D];    // 4
__device__ float g_v[NE * D];    // 5
__device__ float g_ao[NE * D];   // 6
__device__ float g_o[NE * D];    // 7
__device__ float g_hid[NE * D];  // 8
// transposed split-bf16 weights: [w][n][k], w: 0=Wnp 1=Wq 2=Wk 3=Wv 4=Wo 5=W1
__device__ __nv_bfloat16 g_wthi[6 * D * D];
__device__ __nv_bfloat16 g_wtlo[6 * D * D];

template <int ID> __device__ __forceinline__ float* buf();
template <> __device__ __forceinline__ float* buf<2>() { return g_h; }
template <> __device__ __forceinline__ float* buf<3>() { return g_q; }
template <> __device__ __forceinline__ float* buf<4>() { return g_k; }
template <> __device__ __forceinline__ float* buf<5>() { return g_v; }
template <> __device__ __forceinline__ float* buf<6>() { return g_ao; }
template <> __device__ __forceinline__ float* buf<7>() { return g_o; }
template <> __device__ __forceinline__ float* buf<8>() { return g_hid; }

// ================= 1: fused front-end =================
// blocks [0,96)  : weight prep (split-bf16 + transpose), 6 weights x 16 tiles
// blocks [96,112): edge_index convert (self-detecting dtype)
// blocks [112,752): router scores, warp per row (5120 rows exactly)
__global__ void k_front(const float* __restrict__ nf, const float* __restrict__ efi,
                        const int* __restrict__ ei,
                        const float* __restrict__ Wn, const float* __restrict__ bn,
                        const float* __restrict__ We, const float* __restrict__ be,
                        const float* __restrict__ Wnp, const float* __restrict__ Wq,
                        const float* __restrict__ Wk, const float* __restrict__ Wv,
                        const float* __restrict__ Wo, const float* __restrict__ W1) {
    int b = blockIdx.x;
    int tid = threadIdx.x;
    if (b < 96) {
        __shared__ float s[64][65];
        int w = b >> 4, t16 = b & 15;
        const float* W;
        switch (w) {
            case 0: W = Wnp; break;
            case 1: W = Wq; break;
            case 2: W = Wk; break;
            case 3: W = Wv; break;
            case 4: W = Wo; break;
            default: W = W1; break;
        }
        int n0 = (t16 & 3) * 64, k0 = (t16 >> 2) * 64;
        int n4 = (tid & 15) * 4, kr = tid >> 4;
        #pragma unroll
        for (int kk = kr; kk < 64; kk += 16) {
            float4 v = *(const float4*)&W[(size_t)(k0 + kk) * D + n0 + n4];
            s[kk][n4] = v.x;
            s[kk][n4 + 1] = v.y;
            s[kk][n4 + 2] = v.z;
            s[kk][n4 + 3] = v.w;
        }
        __syncthreads();
        int nl = tid >> 2, kq = (tid & 3) * 16;
        __nv_bfloat16 hi[16], lo[16];
        #pragma unroll
        for (int i = 0; i < 16; ++i) {
            float x = s[kq + i][nl];
            hi[i] = __float2bfloat16(x);
            lo[i] = __float2bfloat16(x - __bfloat162float(hi[i]));
        }
        size_t off = (size_t)w * D * D + (size_t)(n0 + nl) * D + k0 + kq;
        *(uint4*)&g_wthi[off] = *(uint4*)&hi[0];
        *(uint4*)&g_wthi[off + 8] = *(uint4*)&hi[8];
        *(uint4*)&g_wtlo[off] = *(uint4*)&lo[0];
        *(uint4*)&g_wtlo[off + 8] = *(uint4*)&lo[8];
    } else if (b < 112) {
        __shared__ int sh[256];
        int acc = 0;
        for (int i = tid; i < 2048; i += 256) acc |= ei[2 * i + 1];
        sh[tid] = acc;
        __syncthreads();
        for (int s2 = 128; s2 > 0; s2 >>= 1) {
            if (tid < s2) sh[tid] |= sh[tid + s2];
            __syncthreads();
        }
        int is64 = (sh[0] == 0) ? 1 : 0;
        int i = (b - 96) * 256 + tid;
        int s, d;
        if (is64) { s = ei[2 * i]; d = ei[2 * (NE + i)]; }
        else      { s = ei[i];     d = ei[NE + i]; }
        g_src[i] = s;
        g_dst[i] = d;
    } else {
        int warp = (b - 112) * 8 + (tid >> 5);
        int lane = tid & 31;
        const float* x;
        const float* w;
        if (warp < NN) { x = nf + (size_t)warp * D; w = Wn; }
        else           { x = efi + (size_t)(warp - NN) * D; w = We; }
        float s = 0.f;
        #pragma unroll
        for (int i = 0; i < D / 32; ++i) s += x[lane + i * 32] * w[lane + i * 32];
        #pragma unroll
        for (int o = 16; o; o >>= 1) s += __shfl_xor_sync(0xffffffffu, s, o);
        if (lane == 0) {
            if (warp < NN) g_nscore[warp] = s + bn[0];
            else           g_escore[warp - NN] = s + be[0];
        }
    }
}

// ================= 2: fused build =================
struct TkSmem {
    unsigned su[NE];
    int hist[256];
    unsigned pref;
    int krem;
    int wagg[32];
};
struct IncSmem {
    int cnt[NN];
    int off[NN];
    int pos[NN];
    int inc[2 * NE];
};
union BuildSmem {
    TkSmem tk;
    IncSmem in;
};

__global__ void __launch_bounds__(1024, 1) k_build() {
    __shared__ BuildSmem sm;
    int tid = threadIdx.x;
    int lane = tid & 31, wid = tid >> 5;

    if (blockIdx.x < 2) {
        const bool is_edge = (blockIdx.x == 1);
        const float* sc = is_edge ? g_escore : g_nscore;
        int* mask = is_edge ? g_emask : g_nmask;
        const int n = is_edge ? NE : NN;
        const int kk = is_edge ? EDGEK : NODEK;
        int items = n >> 10;

        for (int j = 0; j < items; ++j) {
            int i = tid * items + j;
            unsigned bb = __float_as_uint(sc[i]);
            sm.tk.su[i] = (bb & 0x80000000u) ? ~bb : (bb | 0x80000000u);
        }
        if (tid == 0) { sm.tk.pref = 0u; sm.tk.krem = kk; }
        __syncthreads();

        for (int shift = 24; shift >= 0; shift -= 8) {
            unsigned prefix = sm.tk.pref;
            unsigned done_mask = (shift == 24) ? 0u : (0xFFFFFFFFu << (shift + 8));
            if (tid < 256) sm.tk.hist[tid] = 0;
            __syncthreads();
            for (int j = 0; j < items; ++j) {
                unsigned u = sm.tk.su[tid * items + j];
                if ((u & done_mask) == prefix)
                    atomicAdd(&sm.tk.hist[(u >> shift) & 255], 1);
            }
            __syncthreads();
            if (wid == 0) {
                int krem = sm.tk.krem;
                int gsum = 0;
                #pragma unroll
                for (int c = 0; c < 8; ++c) gsum += sm.tk.hist[lane * 8 + c];
                int x = gsum;
                #pragma unroll
                for (int off = 1; off < 32; off <<= 1) {
                    int t = __shfl_down_sync(0xffffffffu, x, off);
                    if (lane + off < 32) x += t;
                }
                int above = x - gsum;
                bool hit = (above < krem) && (x >= krem);
                unsigned bal = __ballot_sync(0xffffffffu, hit);
                int srcl = __ffs(bal) - 1;
                if (lane == srcl) {
                    int cum = above;
                    #pragma unroll
                    for (int c = 7; c >= 0; --c) {
                        int bb = lane * 8 + c;
                        int hc = sm.tk.hist[bb];
                        if (cum + hc >= krem) {
                            sm.tk.pref = prefix | ((unsigned)bb << shift);
                            sm.tk.krem = krem - cum;
                            break;
                        }
                        cum += hc;
                    }
                }
            }
            __syncthreads();
        }
        unsigned T = sm.tk.pref;
        int r = sm.tk.krem;

        int ct = 0;
        for (int j = 0; j < items; ++j) ct += (sm.tk.su[tid * items + j] == T) ? 1 : 0;
        int scan = ct;
        #pragma unroll
        for (int off = 1; off < 32; off <<= 1) {
            int t = __shfl_up_sync(0xffffffffu, scan, off);
            if (lane >= off) scan += t;
        }
        if (lane == 31) sm.tk.wagg[wid] = scan;
        __syncthreads();
        if (wid == 0) {
            int v = sm.tk.wagg[lane];
            #pragma unroll
            for (int off = 1; off < 32; off <<= 1) {
                int t = __shfl_up_sync(0xffffffffu, v, off);
                if (lane >= off) v += t;
            }
            sm.tk.wagg[lane] = v;
        }
        __syncthreads();
        int excl = (wid > 0 ? sm.tk.wagg[wid - 1] : 0) + scan - ct;

        for (int j = 0; j < items; ++j) {
            int i = tid * items + j;
            unsigned u = sm.tk.su[i];
            int mk;
            if (u > T) mk = 1;
            else if (u == T) { mk = (excl < r) ? 1 : 0; excl++; }
            else mk = 0;
            mask[i] = mk;
        }
    } else {
        sm.in.cnt[tid] = 0;
        __syncthreads();
        #pragma unroll
        for (int j = 0; j < 4; ++j) {
            int e = j * 1024 + tid;
            int a = g_src[e], b = g_dst[e];
            atomicAdd(&sm.in.cnt[a], 1);
            if (b != a) atomicAdd(&sm.in.cnt[b], 1);
        }
        __syncthreads();
        int own = sm.in.cnt[tid];
        int val = own;
        for (int dd = 1; dd < 1024; dd <<= 1) {
            int t = (tid >= dd) ? sm.in.cnt[tid - dd] : 0;
            __syncthreads();
            val += t;
            sm.in.cnt[tid] = val;
            __syncthreads();
        }
        int offv = val - own;
        sm.in.off[tid] = offv;
        sm.in.pos[tid] = offv;
        if (tid == 1023) g_off[1024] = val;
        g_off[tid] = offv;
        __syncthreads();
        int total = sm.in.cnt[1023];
        #pragma unroll
        for (int j = 0; j < 4; ++j) {
            int e = j * 1024 + tid;
            int a = g_src[e], b = g_dst[e];
            sm.in.inc[atomicAdd(&sm.in.pos[a], 1)] = e;
            if (b != a) sm.in.inc[atomicAdd(&sm.in.pos[b], 1)] = e;
        }
        __syncthreads();
        {
            int s = sm.in.off[tid];
            int t = sm.in.pos[tid];
            for (int i = s + 1; i < t; ++i) {
                int v = sm.in.inc[i];
                int j = i - 1;
                while (j >= s && sm.in.inc[j] > v) { sm.in.inc[j + 1] = sm.in.inc[j]; --j; }
                sm.in.inc[j + 1] = v;
            }
        }
        __syncthreads();
        for (int i = tid; i < total; i += 1024) g_inc[i] = sm.in.inc[i];
    }
}

// ================= GEMM (split-bf16 mma.sync, K-chunked, 2 CTAs/SM) =================
__device__ __forceinline__ void mma_bf16(float* c, const uint32_t* a, const uint32_t* b) {
    asm volatile(
        "mma.sync.aligned.m16n8k16.row.col.f32.bf16.bf16.f32 "
        "{%0,%1,%2,%3}, {%4,%5,%6,%7}, {%8,%9}, {%0,%1,%2,%3};"
        : "+f"(c[0]), "+f"(c[1]), "+f"(c[2]), "+f"(c[3])
        : "r"(a[0]), "r"(a[1]), "r"(a[2]), "r"(a[3]), "r"(b[0]), "r"(b[1]));
}

__device__ __forceinline__ void split_store_a(__nv_bfloat16* as_hi, __nv_bfloat16* as_lo,
                                              int o, float4 a) {
    __nv_bfloat16 h0 = __float2bfloat16(a.x), h1 = __float2bfloat16(a.y);
    __nv_bfloat16 h2 = __float2bfloat16(a.z), h3 = __float2bfloat16(a.w);
    __nv_bfloat16 l0 = __float2bfloat16(a.x - __bfloat162float(h0));
    __nv_bfloat16 l1 = __float2bfloat16(a.y - __bfloat162float(h1));
    __nv_bfloat16 l2 = __float2bfloat16(a.z - __bfloat162float(h2));
    __nv_bfloat16 l3 = __float2bfloat16(a.w - __bfloat162float(h3));
    *(__nv_bfloat162*)&as_hi[o]     = __nv_bfloat162(h0, h1);
    *(__nv_bfloat162*)&as_hi[o + 2] = __nv_bfloat162(h2, h3);
    *(__nv_bfloat162*)&as_lo[o]     = __nv_bfloat162(l0, l1);
    *(__nv_bfloat162*)&as_lo[o + 2] = __nv_bfloat162(l2, l3);
}

// fill B chunk [64 x 128] from precomputed transposed weights
__device__ __forceinline__ void fill_b_chunk(__nv_bfloat16* bs_hi, __nv_bfloat16* bs_lo,
                                             int wslot, int n0, int kc0, int tid) {
    const __nv_bfloat16* Bh = g_wthi + (size_t)wslot * D * D;
    const __nv_bfloat16* Bl = g_wtlo + (size_t)wslot * D * D;
    #pragma unroll
    for (int it = 0; it < 4; ++it) {
        int idx = it * 256 + tid;            // 1024 uint4 per array
        int n = idx >> 4, kq = (idx & 15) * 8;
        uint4 vh = *(const uint4*)&Bh[(size_t)(n0 + n) * D + kc0 + kq];
        uint4 vl = *(const uint4*)&Bl[(size_t)(n0 + n) * D + kc0 + kq];
        *(uint4*)&bs_hi[n * BPITCH + kq] = vh;
        *(uint4*)&bs_lo[n * BPITCH + kq] = vl;
    }
}

// 8 k-steps over the resident chunk; B fragments loaded inside nf loop (low reg pressure)
__device__ __forceinline__ void mma_chunk(const __nv_bfloat16* as_hi, const __nv_bfloat16* as_lo,
                                          const __nv_bfloat16* bs_hi, const __nv_bfloat16* bs_lo,
                                          int wm, int wn, int g, int t, float acc[2][4][4]) {
    #pragma unroll
    for (int ks = 0; ks < 8; ++ks) {
        int kb = ks * 16;
        uint32_t ah[2][4], al[2][4];
        #pragma unroll
        for (int mf = 0; mf < 2; ++mf) {
            int r = wm * 32 + mf * 16 + g;
            int o0 = r * APITCH + kb + 2 * t;
            int o1 = (r + 8) * APITCH + kb + 2 * t;
            ah[mf][0] = *(const uint32_t*)&as_hi[o0];
            ah[mf][1] = *(const uint32_t*)&as_hi[o1];
            ah[mf][2] = *(const uint32_t*)&as_hi[o0 + 8];
            ah[mf][3] = *(const uint32_t*)&as_hi[o1 + 8];
            al[mf][0] = *(const uint32_t*)&as_lo[o0];
            al[mf][1] = *(const uint32_t*)&as_lo[o1];
            al[mf][2] = *(const uint32_t*)&as_lo[o0 + 8];
            al[mf][3] = *(const uint32_t*)&as_lo[o1 + 8];
        }
        #pragma unroll
        for (int nf = 0; nf < 4; ++nf) {
            int r = wn * 32 + nf * 8 + g;
            int o = r * BPITCH + kb + 2 * t;
            uint32_t bh[2], bl[2];
            bh[0] = *(const uint32_t*)&bs_hi[o];
            bh[1] = *(const uint32_t*)&bs_hi[o + 8];
            bl[0] = *(const uint32_t*)&bs_lo[o];
            bl[1] = *(const uint32_t*)&bs_lo[o + 8];
            #pragma unroll
            for (int mf = 0; mf < 2; ++mf) {
                mma_bf16(acc[mf][nf], ah[mf], bh);
                mma_bf16(acc[mf][nf], ah[mf], bl);
                mma_bf16(acc[mf][nf], al[mf], bh);
            }
        }
    }
}

template <int ACT>
__device__ __forceinline__ void gemm_mma_body(const float* __restrict__ A, int wslot,
                                              const float* __restrict__ bias,
                                              float* __restrict__ C) {
    extern __shared__ __nv_bfloat16 smx[];
    __nv_bfloat16* as_hi = smx + OFF_AHI;
    __nv_bfloat16* as_lo = smx + OFF_ALO;
    __nv_bfloat16* bs_hi = smx + OFF_BHI;
    __nv_bfloat16* bs_lo = smx + OFF_BLO;

    int tid = threadIdx.x;
    int wid = tid >> 5, lane = tid & 31;
    int g = lane >> 2, t = lane & 3;
    int wm = wid >> 1, wn = wid & 1;
    int m0 = blockIdx.y * 128, n0 = blockIdx.x * 64;

    float acc[2][4][4] = {};
    #pragma unroll
    for (int kc = 0; kc < 2; ++kc) {
        int kc0 = kc * KC;
        #pragma unroll
        for (int it = 0; it < 16; ++it) {
            int idx = it * 256 + tid;        // 4096 float4
            int m = idx >> 5, k4 = (idx & 31) * 4;
            float4 a = *(const float4*)&A[(size_t)(m0 + m) * D + kc0 + k4];
            split_store_a(as_hi, as_lo, m * APITCH + k4, a);
        }
        fill_b_chunk(bs_hi, bs_lo, wslot, n0, kc0, tid);
        __syncthreads();
        mma_chunk(as_hi, as_lo, bs_hi, bs_lo, wm, wn, g, t, acc);
        __syncthreads();
    }

    #pragma unroll
    for (int mf = 0; mf < 2; ++mf) {
        int r0 = m0 + wm * 32 + mf * 16 + g;
        #pragma unroll
        for (int nf = 0; nf < 4; ++nf) {
            int c = n0 + wn * 32 + nf * 8 + 2 * t;
            float bb0 = bias[c], bb1 = bias[c + 1];
            #pragma unroll
            for (int half = 0; half < 2; ++half) {
                int r = r0 + half * 8;
                float v0 = acc[mf][nf][half * 2 + 0] + bb0;
                float v1 = acc[mf][nf][half * 2 + 1] + bb1;
                if (ACT == 1) {
                    float x0 = v0, x1 = v1;
                    float t0 = tanhf(0.7978845608028654f * (x0 + 0.044715f * x0 * x0 * x0));
                    float t1 = tanhf(0.7978845608028654f * (x1 + 0.044715f * x1 * x1 * x1));
                    v0 = 0.5f * x0 * (1.0f + t0);
                    v1 = 0.5f * x1 * (1.0f + t1);
                }
                float2 o2 = {v0, v1};
                *(float2*)&C[(size_t)r * D + c] = o2;
            }
        }
    }
}

// gemm h: A generated on the fly (nf[src]+nf[dst]); epilogue adds masked ef
__global__ void __launch_bounds__(256, 2) k_gemm_h(const float* __restrict__ nf,
                                                   const float* __restrict__ efi,
                                                   const float* __restrict__ bias) {
    extern __shared__ __nv_bfloat16 smx[];
    __nv_bfloat16* as_hi = smx + OFF_AHI;
    __nv_bfloat16* as_lo = smx + OFF_ALO;
    __nv_bfloat16* bs_hi = smx + OFF_BHI;
    __nv_bfloat16* bs_lo = smx + OFF_BLO;

    int tid = threadIdx.x;
    int wid = tid >> 5, lane = tid & 31;
    int g = lane >> 2, t = lane & 3;
    int wm = wid >> 1, wn = wid & 1;
    int m0 = blockIdx.y * 128, n0 = blockIdx.x * 64;

    float acc[2][4][4] = {};
    #pragma unroll
    for (int kc = 0; kc < 2; ++kc) {
        int kc0 = kc * KC;
        #pragma unroll
        for (int it = 0; it < 16; ++it) {
            int idx = it * 256 + tid;
            int m = idx >> 5, k4 = (idx & 31) * 4;
            int e = m0 + m;
            int a = g_src[e], b = g_dst[e];
            float4 xa = *(const float4*)&nf[(size_t)a * D + kc0 + k4];
            float4 xb = *(const float4*)&nf[(size_t)b * D + kc0 + k4];
            float4 s = {xa.x + xb.x, xa.y + xb.y, xa.z + xb.z, xa.w + xb.w};
            split_store_a(as_hi, as_lo, m * APITCH + k4, s);
        }
        fill_b_chunk(bs_hi, bs_lo, 0, n0, kc0, tid);
        __syncthreads();
        mma_chunk(as_hi, as_lo, bs_hi, bs_lo, wm, wn, g, t, acc);
        __syncthreads();
    }

    #pragma unroll
    for (int mf = 0; mf < 2; ++mf) {
        int r0 = m0 + wm * 32 + mf * 16 + g;
        #pragma unroll
        for (int half = 0; half < 2; ++half) {
            int r = r0 + half * 8;
            int em = g_emask[r] & g_nmask[g_src[r]] & g_nmask[g_dst[r]];
            float fm = em ? 1.0f : 0.0f;
            #pragma unroll
            for (int nf = 0; nf < 4; ++nf) {
                int c = n0 + wn * 32 + nf * 8 + 2 * t;
                float v0 = acc[mf][nf][half * 2 + 0] + bias[c]
                         + fm * efi[(size_t)r * D + c];
                float v1 = acc[mf][nf][half * 2 + 1] + bias[c + 1]
                         + fm * efi[(size_t)r * D + c + 1];
                float2 o2 = {v0, v1};
                *(float2*)&g_h[(size_t)r * D + c] = o2;
            }
        }
    }
}

template <int ACT, int AID, int CID>
__global__ void __launch_bounds__(256, 2) k_gemm_mma(int wslot, const float* __restrict__ bias) {
    gemm_mma_body<ACT>(buf<AID>(), wslot, bias, buf<CID>());
}

__global__ void __launch_bounds__(256, 2) k_gemm_mma_qkv(
        const float* __restrict__ bq, const float* __restrict__ bk,
        const float* __restrict__ bv) {
    const float* bias;
    float* C;
    if (blockIdx.z == 0)      { bias = bq; C = g_q; }
    else if (blockIdx.z == 1) { bias = bk; C = g_k; }
    else                      { bias = bv; C = g_v; }
    gemm_mma_body<0>(g_h, 1 + blockIdx.z, bias, C);
}

// ================= sparse masked attention =================
__global__ void k_attn() {
    __shared__ int s_cand[MAXC];
    __shared__ float s_sc[HN][MAXC];
    __shared__ int s_n;
    int e = blockIdx.x;
    int tid = threadIdx.x;
    int h = tid >> 5, lane = tid & 31;
    int a = g_src[e], b = g_dst[e];
    int oa = g_off[a];
    int na = g_off[a + 1] - oa;

    for (int i = tid; i < na; i += 128) s_cand[i] = g_inc[oa + i];

    if (tid < 32) {
        int cnt = na;
        if (b != a) {
            int ob = g_off[b];
            int nb = g_off[b + 1] - ob;
            for (int i0 = 0; i0 < nb; i0 += 32) {
                int i = i0 + lane;
                int f = 0, keep = 0;
                if (i < nb) {
                    f = g_inc[ob + i];
                    keep = (g_src[f] != a && g_dst[f] != a) ? 1 : 0;
                }
                unsigned bal = __ballot_sync(0xffffffffu, keep != 0);
                if (keep) {
                    int pos = cnt + __popc(bal & ((1u << lane) - 1u));
                    if (pos < MAXC) s_cand[pos] = f;
                }
                cnt += __popc(bal);
            }
        }
        if (lane == 0) s_n = (cnt < MAXC) ? cnt : MAXC;
    }
    __syncthreads();
    int nc = s_n;
    int base = e * D + h * DHD;

    float2 q2 = *(const float2*)&g_q[base + lane * 2];

    for (int c = 0; c < nc; ++c) {
        int f = s_cand[c];
        float2 k2 = *(const float2*)&g_k[f * D + h * DHD + lane * 2];
        float s = q2.x * k2.x + q2.y * k2.y;
        #pragma unroll
        for (int o = 16; o; o >>= 1) s += __shfl_xor_sync(0xffffffffu, s, o);
        if (lane == 0) s_sc[h][c] = s * 0.125f;
    }
    __syncwarp();

    float mx = -3.0e38f;
    for (int c = lane; c < nc; c += 32) mx = fmaxf(mx, s_sc[h][c]);
    #pragma unroll
    for (int o = 16; o; o >>= 1) mx = fmaxf(mx, __shfl_xor_sync(0xffffffffu, mx, o));
    float l = 0.f;
    for (int c = lane; c < nc; c += 32) {
        float p = __expf(s_sc[h][c] - mx);
        s_sc[h][c] = p;
        l += p;
    }
    #pragma unroll
    for (int o = 16; o; o >>= 1) l += __shfl_xor_sync(0xffffffffu, l, o);
    __syncwarp();

    float ax = 0.f, ay = 0.f;
    for (int c = 0; c < nc; ++c) {
        float p = s_sc[h][c];
        float2 v2 = *(const float2*)&g_v[s_cand[c] * D + h * DHD + lane * 2];
        ax += p * v2.x;
        ay += p * v2.y;
    }
    float inv = 1.f / l;
    float2 r;
    r.x = ax * inv;
    r.y = ay * inv;
    *(float2*)&g_ao[base + lane * 2] = r;
}

// ================= classifier =================
__global__ void k_cls(const float* __restrict__ W2, const float* __restrict__ b2,
                      float* __restrict__ out) {
    int warp = (blockIdx.x * blockDim.x + threadIdx.x) >> 5;
    int lane = threadIdx.x & 31;
    if (warp >= NE) return;
    float x[8];
    #pragma unroll
    for (int i = 0; i < 8; ++i) x[i] = g_hid[(size_t)warp * D + lane + i * 32];
    float res = 0.f;
    #pragma unroll
    for (int c = 0; c < CLS; ++c) {
        float s = 0.f;
        #pragma unroll
        for (int i = 0; i < 8; ++i) s += x[i] * W2[(size_t)(lane + i * 32) * CLS + c];
        #pragma unroll
        for (int o = 16; o; o >>= 1) s += __shfl_xor_sync(0xffffffffu, s, o);
        if (lane == c) res = s + b2[c];
    }
    if (lane < CLS) out[(size_t)warp * CLS + lane] = res;
}

// ================= host =================
extern "C" void kernel_launch(void* const* d_in, const int* in_sizes, int n_in,
                              void* d_out, int out_size) {
    const float* nf   = (const float*)d_in[0];
    const float* efi  = (const float*)d_in[1];
    const int*   ei   = (const int*)d_in[2];
    const float* Wn_r = (const float*)d_in[3];
    const float* bn_r = (const float*)d_in[4];
    const float* We_r = (const float*)d_in[5];
    const float* be_r = (const float*)d_in[6];
    const float* Wnp  = (const float*)d_in[7];
    const float* bnp  = (const float*)d_in[8];
    const float* Wq   = (const float*)d_in[9];
    const float* bq   = (const float*)d_in[10];
    const float* Wk   = (const float*)d_in[11];
    const float* bk   = (const float*)d_in[12];
    const float* Wv   = (const float*)d_in[13];
    const float* bv   = (const float*)d_in[14];
    const float* Wo   = (const float*)d_in[15];
    const float* bo   = (const float*)d_in[16];
    const float* W1   = (const float*)d_in[17];
    const float* b1   = (const float*)d_in[18];
    const float* W2   = (const float*)d_in[19];
    const float* b2   = (const float*)d_in[20];
    float* out = (float*)d_out;

    cudaFuncSetAttribute(k_gemm_h, cudaFuncAttributeMaxDynamicSharedMemorySize, MMA_SMEM_BYTES);
    cudaFuncSetAttribute(k_gemm_mma_qkv, cudaFuncAttributeMaxDynamicSharedMemorySize, MMA_SMEM_BYTES);
    cudaFuncSetAttribute(k_gemm_mma<0, 6, 7>, cudaFuncAttributeMaxDynamicSharedMemorySize, MMA_SMEM_BYTES);
    cudaFuncSetAttribute(k_gemm_mma<1, 7, 8>, cudaFuncAttributeMaxDynamicSharedMemorySize, MMA_SMEM_BYTES);

    k_front<<<752, 256>>>(nf, efi, ei, Wn_r, bn_r, We_r, be_r, Wnp, Wq, Wk, Wv, Wo, W1);
    k_build<<<3, 1024>>>();

    dim3 gg(D / 64, NE / 128);      // (4, 32)
    dim3 gq(D / 64, NE / 128, 3);   // fused q/k/v
    k_gemm_h<<<gg, 256, MMA_SMEM_BYTES>>>(nf, efi, bnp);            // h = (nf[s]+nf[d])@Wnp + bnp + mask*ef
    k_gemm_mma_qkv<<<gq, 256, MMA_SMEM_BYTES>>>(bq, bk, bv);        // q,k,v
    k_attn<<<NE, 128>>>();
    k_gemm_mma<0, 6, 7><<<gg, 256, MMA_SMEM_BYTES>>>(4, bo);        // o = ao@Wo + bo
    k_gemm_mma<1, 7, 8><<<gg, 256, MMA_SMEM_BYTES>>>(5, b1);        // hid = gelu(o@W1 + b1)
    k_cls<<<(NE * 32 + 255) / 256, 256>>>(W2, b2, out);
}